// round 1
// baseline (speedup 1.0000x reference)
#include <cuda_runtime.h>
#include <cstdint>

#define Bn 4
#define Tn 2048
#define Dn 2048
#define Pn 512
#define Kn 16
#define An 4
#define Rn 32
#define NEXC 409   // int(0.8 * 512)

// ---- static scratch (no allocations allowed) ----
__device__ float d_geff_ssm[Pn * Kn];
__device__ float d_geff_mlp[Pn * Kn];
__device__ float d_so_ssm[Pn];
__device__ float d_so_mlp[Pn];
__device__ float g_z  [Bn * Tn * Rn];
__device__ float g_lam[Bn * Tn * Rn];
__device__ float g_S  [Bn * Tn * Rn];

__device__ __forceinline__ float sigmoidf_fast(float u) {
    return 1.0f / (1.0f + __expf(-u));
}

// ---------------------------------------------------------------------------
// Precompute: per-neuron quant scalars and folded gather weights.
//   sp[p]  = sign[p] * mean_k |Wp[p,k]|
//   so[p]  = sign[p] * mean_a |Wout[p,a]|
//   geff[p,k] = sp[p] * wg[p,k] * g[idx[p,k]]
// ---------------------------------------------------------------------------
__global__ void precompute_kernel(
    const float* __restrict__ wg_ssm, const float* __restrict__ wg_mlp,
    const float* __restrict__ Wp_ssm, const float* __restrict__ Wout_ssm,
    const float* __restrict__ Wp_mlp, const float* __restrict__ Wout_mlp,
    const int*   __restrict__ idx_ssm, const int* __restrict__ idx_mlp,
    const float* __restrict__ g1, const float* __restrict__ g2)
{
    int p = threadIdx.x;
    if (p >= Pn) return;
    float sign = (p < NEXC) ? 1.0f : -1.0f;

    float s = 0.f;
    #pragma unroll
    for (int k = 0; k < Kn; k++) s += fabsf(Wp_ssm[p * Kn + k]);
    float sp_ssm = sign * s * (1.0f / Kn);

    s = 0.f;
    #pragma unroll
    for (int a = 0; a < An; a++) s += fabsf(Wout_ssm[p * An + a]);
    d_so_ssm[p] = sign * s * (1.0f / An);

    s = 0.f;
    #pragma unroll
    for (int k = 0; k < Kn; k++) s += fabsf(Wp_mlp[p * Kn + k]);
    float sp_mlp = sign * s * (1.0f / Kn);

    s = 0.f;
    #pragma unroll
    for (int a = 0; a < An; a++) s += fabsf(Wout_mlp[p * An + a]);
    d_so_mlp[p] = sign * s * (1.0f / An);

    #pragma unroll
    for (int k = 0; k < Kn; k++) {
        int ds = idx_ssm[p * Kn + k];
        d_geff_ssm[p * Kn + k] = sp_ssm * wg_ssm[p * Kn + k] * g1[ds];
        int dm = idx_mlp[p * Kn + k];
        d_geff_mlp[p * Kn + k] = sp_mlp * wg_mlp[p * Kn + k] * g2[dm];
    }
}

// ---------------------------------------------------------------------------
// Pass 1: per token -> z[b,t,r], lam[b,t,r]
// ---------------------------------------------------------------------------
__global__ __launch_bounds__(256) void pass1_kernel(
    const float* __restrict__ x, const int* __restrict__ idx_ssm,
    const float* __restrict__ U, const float* __restrict__ Wgate,
    const float* __restrict__ bgate)
{
    __shared__ float sx[Dn];
    __shared__ float tb[Pn];
    __shared__ float fb[Pn];
    __shared__ float red[8];
    __shared__ float red2[2][4][32];
    __shared__ float s_rstd;

    const int tid = threadIdx.x;
    const size_t token = blockIdx.x;
    const float4* xrow = (const float4*)(x + token * (size_t)Dn);

    // load x row + sum of squares
    float ss = 0.f;
    #pragma unroll
    for (int i = 0; i < 2; i++) {
        float4 v = xrow[tid + i * 256];
        ((float4*)sx)[tid + i * 256] = v;
        ss += v.x * v.x + v.y * v.y + v.z * v.z + v.w * v.w;
    }
    #pragma unroll
    for (int o = 16; o; o >>= 1) ss += __shfl_xor_sync(0xffffffffu, ss, o);
    if ((tid & 31) == 0) red[tid >> 5] = ss;
    __syncthreads();
    if (tid == 0) {
        float t = 0.f;
        #pragma unroll
        for (int i = 0; i < 8; i++) t += red[i];
        s_rstd = rsqrtf(t * (1.0f / Dn) + 1e-6f);
    }
    __syncthreads();
    const float rstd = s_rstd;

    // gather-dot: u, f, t = f*u
    #pragma unroll
    for (int pp = 0; pp < 2; pp++) {
        int p = tid + pp * 256;
        const int*   ip = idx_ssm   + p * Kn;
        const float* wp = d_geff_ssm + p * Kn;
        float a0 = 0.f, a1 = 0.f;
        #pragma unroll
        for (int k = 0; k < Kn; k += 2) {
            a0 += sx[ip[k]]     * wp[k];
            a1 += sx[ip[k + 1]] * wp[k + 1];
        }
        float u = rstd * (a0 + a1);
        float f = sigmoidf_fast(u);
        fb[p] = f;
        tb[p] = f * u;
    }
    __syncthreads();

    // einsum: z[r] = sum_p t[p]*U[p,r] ; g[r] = sum_p f[p]*Wgate[p,r]
    const int which  = tid >> 7;        // 0 -> z, 1 -> gate
    const int stripe = (tid >> 5) & 3;  // p-stripe of 128
    const int r      = tid & 31;
    const float* buf   = which ? fb : tb;
    const float* Wb    = (which ? Wgate : U) + (size_t)(stripe * 128) * Rn + r;
    const float* bbase = buf + stripe * 128;
    float a0 = 0.f, a1 = 0.f, a2 = 0.f, a3 = 0.f;
    #pragma unroll 8
    for (int p = 0; p < 128; p += 4) {
        a0 += bbase[p]     * Wb[(p)     * Rn];
        a1 += bbase[p + 1] * Wb[(p + 1) * Rn];
        a2 += bbase[p + 2] * Wb[(p + 2) * Rn];
        a3 += bbase[p + 3] * Wb[(p + 3) * Rn];
    }
    red2[which][stripe][r] = (a0 + a1) + (a2 + a3);
    __syncthreads();
    if (tid < 64) {
        int wh = tid >> 5, rr = tid & 31;
        float v = red2[wh][0][rr] + red2[wh][1][rr] + red2[wh][2][rr] + red2[wh][3][rr];
        size_t o = token * Rn + rr;
        if (wh == 0) g_z[o] = v;
        else         g_lam[o] = sigmoidf_fast(v + bgate[rr]);
    }
}

// ---------------------------------------------------------------------------
// Scan: s_t = lam_t * s_{t-1} + z_t   per (b,r). Parallel affine scan.
// Block = one batch b. 1024 threads = (chunk 0..31) x (r 0..31), 64 t/chunk.
// ---------------------------------------------------------------------------
__global__ __launch_bounds__(1024) void scan_kernel(
    const float* __restrict__ state, float* __restrict__ state_out)
{
    const int b = blockIdx.x;
    const int tid = threadIdx.x;
    const int r = tid & 31;
    const int chunk = tid >> 5;
    const int CH = Tn / 32;   // 64
    const size_t base = (size_t)b * Tn * Rn;
    const int t0 = chunk * CH;

    // compose 64 affines: (a,bb) = step_{t0+63} o ... o step_{t0}
    float a = 1.0f, bb = 0.0f;
    for (int j = 0; j < CH; j++) {
        size_t o = base + (size_t)(t0 + j) * Rn + r;
        float l = g_lam[o], zv = g_z[o];
        bb = l * bb + zv;
        a  = l * a;
    }

    __shared__ float sa[32][33];
    __shared__ float sb[32][33];
    sa[chunk][r] = a;
    sb[chunk][r] = bb;
    __syncthreads();

    // warp w scans dimension r=w across the 32 chunks (lane = chunk)
    {
        int w = tid >> 5;   // r index for this warp
        int c = tid & 31;   // chunk index
        float A = sa[c][w], Bv = sb[c][w];
        #pragma unroll
        for (int off = 1; off < 32; off <<= 1) {
            float Ap = __shfl_up_sync(0xffffffffu, A,  off);
            float Bp = __shfl_up_sync(0xffffffffu, Bv, off);
            if (c >= off) {            // new = cur o prev
                Bv = A * Bp + Bv;
                A  = A * Ap;
            }
        }
        sa[c][w] = A;                  // inclusive prefix through chunk c
        sb[c][w] = Bv;
    }
    __syncthreads();

    // replay: start state = prefix(chunk-1) applied to s0
    float s0 = state[b * Rn + r];
    float s = (chunk == 0) ? s0 : (sa[chunk - 1][r] * s0 + sb[chunk - 1][r]);
    for (int j = 0; j < CH; j++) {
        size_t o = base + (size_t)(t0 + j) * Rn + r;
        float l = g_lam[o], zv = g_z[o];
        s = l * s + zv;
        g_S[o] = s;
    }
    if (chunk == 31 && state_out != nullptr)
        state_out[b * Rn + r] = s;
}

// ---------------------------------------------------------------------------
// Pass 3: per token -> x_out. Recomputes f_ssm, forms x_after, does MLP.
// ---------------------------------------------------------------------------
__global__ __launch_bounds__(256) void pass3_kernel(
    const float* __restrict__ x, const int* __restrict__ idx_ssm,
    const int* __restrict__ idx_mlp, const float* __restrict__ V,
    float* __restrict__ out)
{
    __shared__ float sx[Dn];
    __shared__ float cb[Pn];
    __shared__ float sS[Rn];
    __shared__ float red[8];
    __shared__ float s_rstd;

    const int tid = threadIdx.x;
    const size_t token = blockIdx.x;
    const float4* xrow = (const float4*)(x + token * (size_t)Dn);

    float ss = 0.f;
    #pragma unroll
    for (int i = 0; i < 2; i++) {
        float4 v = xrow[tid + i * 256];
        ((float4*)sx)[tid + i * 256] = v;
        ss += v.x * v.x + v.y * v.y + v.z * v.z + v.w * v.w;
    }
    if (tid < 32) sS[tid] = g_S[token * Rn + tid];
    #pragma unroll
    for (int o = 16; o; o >>= 1) ss += __shfl_xor_sync(0xffffffffu, ss, o);
    if ((tid & 31) == 0) red[tid >> 5] = ss;
    __syncthreads();
    if (tid == 0) {
        float t = 0.f;
        #pragma unroll
        for (int i = 0; i < 8; i++) t += red[i];
        s_rstd = rsqrtf(t * (1.0f / Dn) + 1e-6f);
    }
    __syncthreads();
    const float rstd1 = s_rstd;

    // tilde = S . V ; recompute f_ssm ; c[p] = f*tilde*so
    #pragma unroll
    for (int pp = 0; pp < 2; pp++) {
        int p = tid + pp * 256;
        float tl = 0.f;
        #pragma unroll
        for (int rr = 0; rr < Rn; rr++) tl += sS[rr] * V[rr * Pn + p];
        const int*   ip = idx_ssm    + p * Kn;
        const float* wp = d_geff_ssm + p * Kn;
        float a0 = 0.f, a1 = 0.f;
        #pragma unroll
        for (int k = 0; k < Kn; k += 2) {
            a0 += sx[ip[k]]     * wp[k];
            a1 += sx[ip[k + 1]] * wp[k + 1];
        }
        float u = rstd1 * (a0 + a1);
        float f = sigmoidf_fast(u);
        cb[p] = f * tl * d_so_ssm[p];
    }
    __syncthreads();

    // x_after = x + broadcast(c); new sumsq   (float4 group i == neuron p=i)
    float ss2 = 0.f;
    #pragma unroll
    for (int i = 0; i < 2; i++) {
        int g = tid + i * 256;
        float4 v = ((float4*)sx)[g];
        float c = cb[g];
        v.x += c; v.y += c; v.z += c; v.w += c;
        ((float4*)sx)[g] = v;
        ss2 += v.x * v.x + v.y * v.y + v.z * v.z + v.w * v.w;
    }
    __syncthreads();   // all x_after in smem, all cb reads done

    #pragma unroll
    for (int o = 16; o; o >>= 1) ss2 += __shfl_xor_sync(0xffffffffu, ss2, o);
    if ((tid & 31) == 0) red[tid >> 5] = ss2;
    __syncthreads();
    if (tid == 0) {
        float t = 0.f;
        #pragma unroll
        for (int i = 0; i < 8; i++) t += red[i];
        s_rstd = rsqrtf(t * (1.0f / Dn) + 1e-6f);
    }
    __syncthreads();
    const float rstd2 = s_rstd;

    // MLP branch on x_after
    #pragma unroll
    for (int pp = 0; pp < 2; pp++) {
        int p = tid + pp * 256;
        const int*   ip = idx_mlp    + p * Kn;
        const float* wp = d_geff_mlp + p * Kn;
        float a0 = 0.f, a1 = 0.f;
        #pragma unroll
        for (int k = 0; k < Kn; k += 2) {
            a0 += sx[ip[k]]     * wp[k];
            a1 += sx[ip[k + 1]] * wp[k + 1];
        }
        float u = rstd2 * (a0 + a1);
        float f = sigmoidf_fast(u);
        cb[p] = f * u * d_so_mlp[p];
    }
    __syncthreads();

    float4* orow = (float4*)(out + token * (size_t)Dn);
    #pragma unroll
    for (int i = 0; i < 2; i++) {
        int g = tid + i * 256;
        float4 v = ((float4*)sx)[g];
        float c = cb[g];
        v.x += c; v.y += c; v.z += c; v.w += c;
        orow[g] = v;
    }
}

// ---------------------------------------------------------------------------
extern "C" void kernel_launch(void* const* d_in, const int* in_sizes, int n_in,
                              void* d_out, int out_size)
{
    const float* x        = (const float*)d_in[0];
    const float* state    = (const float*)d_in[1];
    const float* g1       = (const float*)d_in[2];
    const float* g2       = (const float*)d_in[3];
    const int*   idx_ssm  = (const int*)  d_in[4];
    const float* wg_ssm   = (const float*)d_in[5];
    const int*   idx_mlp  = (const int*)  d_in[6];
    const float* wg_mlp   = (const float*)d_in[7];
    const float* Wp_ssm   = (const float*)d_in[8];
    const float* Wout_ssm = (const float*)d_in[9];
    const float* Wp_mlp   = (const float*)d_in[10];
    const float* Wout_mlp = (const float*)d_in[11];
    const float* U        = (const float*)d_in[12];
    const float* V        = (const float*)d_in[13];
    const float* Wgate    = (const float*)d_in[14];
    const float* bgate    = (const float*)d_in[15];
    float* out = (float*)d_out;

    // new_state goes after x_out if the output buffer holds both
    float* state_out = (out_size >= Bn * Tn * Dn + Bn * Rn)
                     ? (out + (size_t)Bn * Tn * Dn) : nullptr;

    precompute_kernel<<<1, 512>>>(wg_ssm, wg_mlp, Wp_ssm, Wout_ssm,
                                  Wp_mlp, Wout_mlp, idx_ssm, idx_mlp, g1, g2);
    pass1_kernel<<<Bn * Tn, 256>>>(x, idx_ssm, U, Wgate, bgate);
    scan_kernel<<<Bn, 1024>>>(state, state_out);
    pass3_kernel<<<Bn * Tn, 256>>>(x, idx_ssm, idx_mlp, V, out);
}

// round 2
// speedup vs baseline: 6.1338x; 6.1338x over previous
#include <cuda_runtime.h>
#include <cstdint>

#define Bn 4
#define Tn 2048
#define Dn 2048
#define Pn 512
#define Kn 16
#define Rn 32
#define NEXC 409   // int(0.8 * 512)

// ---- static scratch (no allocations allowed) ----
__device__ int2  d_pw_ssm[Kn * Pn];   // transposed packed (idx, weight-bits)
__device__ int2  d_pw_mlp[Kn * Pn];
__device__ float d_so_ssm[Pn];
__device__ float d_so_mlp[Pn];
__device__ float g_z  [Bn * Rn * Tn];   // [b][r][t]
__device__ float g_lam[Bn * Rn * Tn];
__device__ float g_S  [Bn * Rn * Tn];
__device__ float g_f  [(size_t)Bn * Tn * Pn];  // [token][p]

__device__ __forceinline__ float sigmoidf_fast(float u) {
    return 1.0f / (1.0f + __expf(-u));
}

// ---------------------------------------------------------------------------
// Precompute: quant scalars + transposed packed gather tables.
//   geff[p,k] = sp[p] * wg[p,k] * g[idx[p,k]],  pw[k][p] = (idx, geff bits)
// ---------------------------------------------------------------------------
__global__ void precompute_kernel(
    const float* __restrict__ wg_ssm, const float* __restrict__ wg_mlp,
    const float* __restrict__ Wp_ssm, const float* __restrict__ Wout_ssm,
    const float* __restrict__ Wp_mlp, const float* __restrict__ Wout_mlp,
    const int*   __restrict__ idx_ssm, const int* __restrict__ idx_mlp,
    const float* __restrict__ g1, const float* __restrict__ g2)
{
    int p = threadIdx.x;
    if (p >= Pn) return;
    float sign = (p < NEXC) ? 1.0f : -1.0f;

    float s = 0.f;
    #pragma unroll
    for (int k = 0; k < Kn; k++) s += fabsf(Wp_ssm[p * Kn + k]);
    float sp_ssm = sign * s * (1.0f / Kn);

    s = 0.f;
    #pragma unroll
    for (int a = 0; a < 4; a++) s += fabsf(Wout_ssm[p * 4 + a]);
    d_so_ssm[p] = sign * s * 0.25f;

    s = 0.f;
    #pragma unroll
    for (int k = 0; k < Kn; k++) s += fabsf(Wp_mlp[p * Kn + k]);
    float sp_mlp = sign * s * (1.0f / Kn);

    s = 0.f;
    #pragma unroll
    for (int a = 0; a < 4; a++) s += fabsf(Wout_mlp[p * 4 + a]);
    d_so_mlp[p] = sign * s * 0.25f;

    #pragma unroll
    for (int k = 0; k < Kn; k++) {
        int ds = idx_ssm[p * Kn + k];
        float ws = sp_ssm * wg_ssm[p * Kn + k] * g1[ds];
        d_pw_ssm[k * Pn + p] = make_int2(ds, __float_as_int(ws));
        int dm = idx_mlp[p * Kn + k];
        float wm = sp_mlp * wg_mlp[p * Kn + k] * g2[dm];
        d_pw_mlp[k * Pn + p] = make_int2(dm, __float_as_int(wm));
    }
}

// ---------------------------------------------------------------------------
// Pass 1: 4 tokens/block -> f (stored), z[b][r][t], lam[b][r][t]
// ---------------------------------------------------------------------------
__global__ __launch_bounds__(256) void pass1_kernel(
    const float* __restrict__ x,
    const float* __restrict__ U, const float* __restrict__ Wgate,
    const float* __restrict__ bgate)
{
    __shared__ __align__(16) unsigned char smem_buf[49152];
    float4* sx4  = (float4*)smem_buf;               // [2048]  x interleaved over 4 tokens
    float4* tb4  = (float4*)(smem_buf + 32768);     // [512]   t = f*u
    float4* fb4  = (float4*)(smem_buf + 40960);     // [512]   f
    float (*red)[4] = (float(*)[4])(smem_buf + 32768);  // aliases tb4 (used before)
    float4 (*red2)[4][32] = (float4(*)[4][32])smem_buf; // aliases sx4 (used after)

    const int tid = threadIdx.x;
    const size_t tok0 = (size_t)blockIdx.x * 4;
    const int b = (int)(tok0 >> 11);
    const int tloc0 = (int)(tok0 & (Tn - 1));
    const float* x0 = x + tok0 * Dn;

    // ---- load 4 x rows interleaved + per-token sumsq ----
    float ss0 = 0.f, ss1 = 0.f, ss2 = 0.f, ss3 = 0.f;
    #pragma unroll
    for (int i = 0; i < 8; i++) {
        int d = tid + i * 256;
        float v0 = x0[d], v1 = x0[Dn + d], v2 = x0[2 * Dn + d], v3 = x0[3 * Dn + d];
        sx4[d] = make_float4(v0, v1, v2, v3);
        ss0 += v0 * v0; ss1 += v1 * v1; ss2 += v2 * v2; ss3 += v3 * v3;
    }
    #pragma unroll
    for (int o = 16; o; o >>= 1) {
        ss0 += __shfl_xor_sync(~0u, ss0, o); ss1 += __shfl_xor_sync(~0u, ss1, o);
        ss2 += __shfl_xor_sync(~0u, ss2, o); ss3 += __shfl_xor_sync(~0u, ss3, o);
    }
    if ((tid & 31) == 0) {
        int w = tid >> 5;
        red[w][0] = ss0; red[w][1] = ss1; red[w][2] = ss2; red[w][3] = ss3;
    }
    __syncthreads();
    float t0s = 0.f, t1s = 0.f, t2s = 0.f, t3s = 0.f;
    #pragma unroll
    for (int w = 0; w < 8; w++) {
        t0s += red[w][0]; t1s += red[w][1]; t2s += red[w][2]; t3s += red[w][3];
    }
    const float4 rst = make_float4(rsqrtf(t0s * (1.0f / Dn) + 1e-6f),
                                   rsqrtf(t1s * (1.0f / Dn) + 1e-6f),
                                   rsqrtf(t2s * (1.0f / Dn) + 1e-6f),
                                   rsqrtf(t3s * (1.0f / Dn) + 1e-6f));
    __syncthreads();   // red reads done before tb4 writes

    // ---- gather-dot: u, f, t for 4 tokens at once ----
    #pragma unroll
    for (int pp = 0; pp < 2; pp++) {
        int p = tid + pp * 256;
        float4 a = make_float4(0.f, 0.f, 0.f, 0.f);
        #pragma unroll
        for (int k = 0; k < Kn; k++) {
            int2 e = d_pw_ssm[k * Pn + p];
            float w = __int_as_float(e.y);
            float4 xv = sx4[e.x];
            a.x += xv.x * w; a.y += xv.y * w; a.z += xv.z * w; a.w += xv.w * w;
        }
        float4 u = make_float4(a.x * rst.x, a.y * rst.y, a.z * rst.z, a.w * rst.w);
        float4 f = make_float4(sigmoidf_fast(u.x), sigmoidf_fast(u.y),
                               sigmoidf_fast(u.z), sigmoidf_fast(u.w));
        fb4[p] = f;
        tb4[p] = make_float4(f.x * u.x, f.y * u.y, f.z * u.z, f.w * u.w);
        g_f[(tok0 + 0) * Pn + p] = f.x;
        g_f[(tok0 + 1) * Pn + p] = f.y;
        g_f[(tok0 + 2) * Pn + p] = f.z;
        g_f[(tok0 + 3) * Pn + p] = f.w;
    }
    __syncthreads();

    // ---- einsum: z[r] = t . U[:,r] ; pre-gate[r] = f . Wgate[:,r] ----
    const int which  = tid >> 7;        // warp-uniform
    const int stripe = (tid >> 5) & 3;
    const int r      = tid & 31;
    const float* Wb = (which ? Wgate : U) + (size_t)(stripe * 128) * Rn + r;
    const float4* buf = (which ? fb4 : tb4) + stripe * 128;
    float4 acc = make_float4(0.f, 0.f, 0.f, 0.f);
    #pragma unroll 8
    for (int p = 0; p < 128; p++) {
        float w = Wb[p * Rn];
        float4 t = buf[p];
        acc.x += t.x * w; acc.y += t.y * w; acc.z += t.z * w; acc.w += t.w * w;
    }
    red2[which][stripe][r] = acc;   // lives in dead sx4 region
    __syncthreads();
    if (tid < 64) {
        int wh = tid >> 5, rr = tid & 31;
        float4 a0 = red2[wh][0][rr], a1 = red2[wh][1][rr];
        float4 a2 = red2[wh][2][rr], a3 = red2[wh][3][rr];
        float4 v = make_float4(a0.x + a1.x + a2.x + a3.x, a0.y + a1.y + a2.y + a3.y,
                               a0.z + a1.z + a2.z + a3.z, a0.w + a1.w + a2.w + a3.w);
        size_t o = ((size_t)(b * Rn + rr)) * Tn + tloc0;
        if (wh == 0) {
            *(float4*)(g_z + o) = v;
        } else {
            float bg = bgate[rr];
            float4 l = make_float4(sigmoidf_fast(v.x + bg), sigmoidf_fast(v.y + bg),
                                   sigmoidf_fast(v.z + bg), sigmoidf_fast(v.w + bg));
            *(float4*)(g_lam + o) = l;
        }
    }
}

// ---------------------------------------------------------------------------
// Scan: one block per (b,r), 256 threads x 8 steps, block-level affine scan.
// ---------------------------------------------------------------------------
__global__ __launch_bounds__(256) void scan_kernel(
    const float* __restrict__ state, float* __restrict__ state_out)
{
    const int br = blockIdx.x;         // b*32 + r
    const int b = br >> 5, r = br & 31;
    const size_t base = (size_t)br * Tn;
    const int tid = threadIdx.x;
    const int t0 = tid * 8;

    float4 za = *(const float4*)(g_z + base + t0);
    float4 zb = *(const float4*)(g_z + base + t0 + 4);
    float4 la = *(const float4*)(g_lam + base + t0);
    float4 lb = *(const float4*)(g_lam + base + t0 + 4);

    // compose 8 affines in time order: s -> a*s + bb
    float a = la.x, bb = za.x;
    bb = la.y * bb + za.y;  a = la.y * a;
    bb = la.z * bb + za.z;  a = la.z * a;
    bb = la.w * bb + za.w;  a = la.w * a;
    bb = lb.x * bb + zb.x;  a = lb.x * a;
    bb = lb.y * bb + zb.y;  a = lb.y * a;
    bb = lb.z * bb + zb.z;  a = lb.z * a;
    bb = lb.w * bb + zb.w;  a = lb.w * a;

    // warp inclusive scan (composition)
    const int lane = tid & 31, wid = tid >> 5;
    float A = a, Bv = bb;
    #pragma unroll
    for (int off = 1; off < 32; off <<= 1) {
        float Ap = __shfl_up_sync(~0u, A, off);
        float Bp = __shfl_up_sync(~0u, Bv, off);
        if (lane >= off) { Bv = A * Bp + Bv; A = A * Ap; }
    }
    __shared__ float wa[8], wb[8];
    if (lane == 31) { wa[wid] = A; wb[wid] = Bv; }
    __syncthreads();

    // warp-exclusive prefix (composite of warps 0..wid-1)
    float pa = 1.f, pb = 0.f;
    #pragma unroll
    for (int w = 0; w < 8; w++) {
        if (w < wid) { pb = wa[w] * pb + wb[w]; pa = wa[w] * pa; }
    }
    // lane-exclusive within warp
    float Aex = __shfl_up_sync(~0u, A, 1);
    float Bex = __shfl_up_sync(~0u, Bv, 1);
    if (lane == 0) { Aex = 1.f; Bex = 0.f; }

    const float s0 = state[b * Rn + r];
    float s = Aex * (pa * s0 + pb) + Bex;

    // replay and store S
    float4 o0, o1;
    s = la.x * s + za.x; o0.x = s;
    s = la.y * s + za.y; o0.y = s;
    s = la.z * s + za.z; o0.z = s;
    s = la.w * s + za.w; o0.w = s;
    s = lb.x * s + zb.x; o1.x = s;
    s = lb.y * s + zb.y; o1.y = s;
    s = lb.z * s + zb.z; o1.z = s;
    s = lb.w * s + zb.w; o1.w = s;
    *(float4*)(g_S + base + t0) = o0;
    *(float4*)(g_S + base + t0 + 4) = o1;

    if (tid == 255 && state_out != nullptr)
        state_out[b * Rn + r] = s;
}

// ---------------------------------------------------------------------------
// Pass 3: 4 tokens/block. Uses stored f_ssm (no SSM gather, no first rmsnorm).
// ---------------------------------------------------------------------------
__global__ __launch_bounds__(256) void pass3_kernel(
    const float* __restrict__ x, const float* __restrict__ V,
    float* __restrict__ out)
{
    __shared__ __align__(16) float4 sx4[Dn];   // 32 KB
    __shared__ float4 cb4[Pn];                 // 8 KB
    __shared__ float sS[4][32];
    __shared__ float red[8][4];
    __shared__ float s_rstd[4];

    const int tid = threadIdx.x;
    const size_t tok0 = (size_t)blockIdx.x * 4;
    const int b = (int)(tok0 >> 11);
    const int tloc0 = (int)(tok0 & (Tn - 1));
    const float* x0 = x + tok0 * Dn;

    #pragma unroll
    for (int i = 0; i < 8; i++) {
        int d = tid + i * 256;
        sx4[d] = make_float4(x0[d], x0[Dn + d], x0[2 * Dn + d], x0[3 * Dn + d]);
    }
    if (tid < 128) {
        int rr = tid >> 2, tt = tid & 3;
        sS[tt][rr] = g_S[((size_t)(b * Rn + rr)) * Tn + tloc0 + tt];
    }
    __syncthreads();

    // c[p] = f_ssm * (S . V[:,p]) * so
    #pragma unroll
    for (int pp = 0; pp < 2; pp++) {
        int p = tid + pp * 256;
        float4 tl = make_float4(0.f, 0.f, 0.f, 0.f);
        #pragma unroll
        for (int rr = 0; rr < Rn; rr++) {
            float w = V[rr * Pn + p];
            tl.x += sS[0][rr] * w; tl.y += sS[1][rr] * w;
            tl.z += sS[2][rr] * w; tl.w += sS[3][rr] * w;
        }
        float so = d_so_ssm[p];
        float f0 = g_f[(tok0 + 0) * Pn + p];
        float f1 = g_f[(tok0 + 1) * Pn + p];
        float f2 = g_f[(tok0 + 2) * Pn + p];
        float f3 = g_f[(tok0 + 3) * Pn + p];
        cb4[p] = make_float4(f0 * tl.x * so, f1 * tl.y * so,
                             f2 * tl.z * so, f3 * tl.w * so);
    }
    __syncthreads();

    // x_after = x + broadcast(c)  (p = d>>2; float4-over-token vector add)
    float ss0 = 0.f, ss1 = 0.f, ss2 = 0.f, ss3 = 0.f;
    #pragma unroll
    for (int i = 0; i < 8; i++) {
        int d = tid + i * 256;
        float4 v = sx4[d];
        float4 c = cb4[d >> 2];
        v.x += c.x; v.y += c.y; v.z += c.z; v.w += c.w;
        sx4[d] = v;
        ss0 += v.x * v.x; ss1 += v.y * v.y; ss2 += v.z * v.z; ss3 += v.w * v.w;
    }
    #pragma unroll
    for (int o = 16; o; o >>= 1) {
        ss0 += __shfl_xor_sync(~0u, ss0, o); ss1 += __shfl_xor_sync(~0u, ss1, o);
        ss2 += __shfl_xor_sync(~0u, ss2, o); ss3 += __shfl_xor_sync(~0u, ss3, o);
    }
    if ((tid & 31) == 0) {
        int w = tid >> 5;
        red[w][0] = ss0; red[w][1] = ss1; red[w][2] = ss2; red[w][3] = ss3;
    }
    __syncthreads();
    if (tid < 4) {
        float t = 0.f;
        #pragma unroll
        for (int w = 0; w < 8; w++) t += red[w][tid];
        s_rstd[tid] = rsqrtf(t * (1.0f / Dn) + 1e-6f);
    }
    __syncthreads();
    const float4 rst = make_float4(s_rstd[0], s_rstd[1], s_rstd[2], s_rstd[3]);

    // MLP gather on x_after
    #pragma unroll
    for (int pp = 0; pp < 2; pp++) {
        int p = tid + pp * 256;
        float4 a = make_float4(0.f, 0.f, 0.f, 0.f);
        #pragma unroll
        for (int k = 0; k < Kn; k++) {
            int2 e = d_pw_mlp[k * Pn + p];
            float w = __int_as_float(e.y);
            float4 xv = sx4[e.x];
            a.x += xv.x * w; a.y += xv.y * w; a.z += xv.z * w; a.w += xv.w * w;
        }
        float4 u = make_float4(a.x * rst.x, a.y * rst.y, a.z * rst.z, a.w * rst.w);
        float4 f = make_float4(sigmoidf_fast(u.x), sigmoidf_fast(u.y),
                               sigmoidf_fast(u.z), sigmoidf_fast(u.w));
        float so = d_so_mlp[p];
        cb4[p] = make_float4(f.x * u.x * so, f.y * u.y * so,
                             f.z * u.z * so, f.w * u.w * so);
    }
    __syncthreads();

    // x_out = x_after + broadcast(c_mlp), coalesced per-token stores
    #pragma unroll
    for (int i = 0; i < 8; i++) {
        int d = tid + i * 256;
        float4 v = sx4[d];
        float4 c = cb4[d >> 2];
        out[(tok0 + 0) * Dn + d] = v.x + c.x;
        out[(tok0 + 1) * Dn + d] = v.y + c.y;
        out[(tok0 + 2) * Dn + d] = v.z + c.z;
        out[(tok0 + 3) * Dn + d] = v.w + c.w;
    }
}

// ---------------------------------------------------------------------------
extern "C" void kernel_launch(void* const* d_in, const int* in_sizes, int n_in,
                              void* d_out, int out_size)
{
    const float* x        = (const float*)d_in[0];
    const float* state    = (const float*)d_in[1];
    const float* g1       = (const float*)d_in[2];
    const float* g2       = (const float*)d_in[3];
    const int*   idx_ssm  = (const int*)  d_in[4];
    const float* wg_ssm   = (const float*)d_in[5];
    const int*   idx_mlp  = (const int*)  d_in[6];
    const float* wg_mlp   = (const float*)d_in[7];
    const float* Wp_ssm   = (const float*)d_in[8];
    const float* Wout_ssm = (const float*)d_in[9];
    const float* Wp_mlp   = (const float*)d_in[10];
    const float* Wout_mlp = (const float*)d_in[11];
    const float* U        = (const float*)d_in[12];
    const float* V        = (const float*)d_in[13];
    const float* Wgate    = (const float*)d_in[14];
    const float* bgate    = (const float*)d_in[15];
    float* out = (float*)d_out;

    float* state_out = (out_size >= Bn * Tn * Dn + Bn * Rn)
                     ? (out + (size_t)Bn * Tn * Dn) : nullptr;

    precompute_kernel<<<1, 512>>>(wg_ssm, wg_mlp, Wp_ssm, Wout_ssm,
                                  Wp_mlp, Wout_mlp, idx_ssm, idx_mlp, g1, g2);
    pass1_kernel<<<Bn * Tn / 4, 256>>>(x, U, Wgate, bgate);
    scan_kernel<<<Bn * Rn, 256>>>(state, state_out);
    pass3_kernel<<<Bn * Tn / 4, 256>>>(x, V, out);
}

// round 6
// speedup vs baseline: 6.2008x; 1.0109x over previous
#include <cuda_runtime.h>
#include <cuda_fp16.h>
#include <cuda_bf16.h>
#include <cstdint>

#define Bn 4
#define Tn 2048
#define Dn 2048
#define Pn 512
#define Kn 16
#define Rn 32
#define NEXC 409   // int(0.8 * 512)

// ---- static scratch (no allocations allowed) ----
__device__ int2   d_pw_ssm[Kn * Pn];   // transposed packed (idx, weight-bits)
__device__ int2   d_pw_mlp[Kn * Pn];
__device__ float  d_so_ssm[Pn];
__device__ float  d_so_mlp[Pn];
__device__ float  g_z  [Bn * Rn * Tn];   // [b][r][t]
__device__ float  g_lam[Bn * Rn * Tn];
__device__ float  g_S  [Bn * Rn * Tn];
__device__ __half g_f  [(size_t)Bn * Tn * Pn];  // [token][p]

__device__ __forceinline__ float sigmoidf_fast(float u) {
    return 1.0f / (1.0f + __expf(-u));
}

// pack 4 floats -> 2x bf16x2 (low half = first value)
__device__ __forceinline__ uint2 pack_bf16x4(float a, float b, float c, float d) {
    __nv_bfloat162 p0 = __floats2bfloat162_rn(a, b);
    __nv_bfloat162 p1 = __floats2bfloat162_rn(c, d);
    uint2 r;
    r.x = *reinterpret_cast<unsigned int*>(&p0);
    r.y = *reinterpret_cast<unsigned int*>(&p1);
    return r;
}

// ---------------------------------------------------------------------------
// Precompute: quant scalars + transposed packed gather tables.
// ---------------------------------------------------------------------------
__global__ void precompute_kernel(
    const float* __restrict__ wg_ssm, const float* __restrict__ wg_mlp,
    const float* __restrict__ Wp_ssm, const float* __restrict__ Wout_ssm,
    const float* __restrict__ Wp_mlp, const float* __restrict__ Wout_mlp,
    const int*   __restrict__ idx_ssm, const int* __restrict__ idx_mlp,
    const float* __restrict__ g1, const float* __restrict__ g2)
{
    int p = threadIdx.x;
    if (p >= Pn) return;
    float sign = (p < NEXC) ? 1.0f : -1.0f;

    float s = 0.f;
    #pragma unroll
    for (int k = 0; k < Kn; k++) s += fabsf(Wp_ssm[p * Kn + k]);
    float sp_ssm = sign * s * (1.0f / Kn);

    s = 0.f;
    #pragma unroll
    for (int a = 0; a < 4; a++) s += fabsf(Wout_ssm[p * 4 + a]);
    d_so_ssm[p] = sign * s * 0.25f;

    s = 0.f;
    #pragma unroll
    for (int k = 0; k < Kn; k++) s += fabsf(Wp_mlp[p * Kn + k]);
    float sp_mlp = sign * s * (1.0f / Kn);

    s = 0.f;
    #pragma unroll
    for (int a = 0; a < 4; a++) s += fabsf(Wout_mlp[p * 4 + a]);
    d_so_mlp[p] = sign * s * 0.25f;

    #pragma unroll
    for (int k = 0; k < Kn; k++) {
        int ds = idx_ssm[p * Kn + k];
        float ws = sp_ssm * wg_ssm[p * Kn + k] * g1[ds];
        d_pw_ssm[k * Pn + p] = make_int2(ds, __float_as_int(ws));
        int dm = idx_mlp[p * Kn + k];
        float wm = sp_mlp * wg_mlp[p * Kn + k] * g2[dm];
        d_pw_mlp[k * Pn + p] = make_int2(dm, __float_as_int(wm));
    }
}

// ---------------------------------------------------------------------------
// Pass 1: 4 tokens/block. FP32 gathers (state path is precision-critical).
// f stored fp16 (only feeds x_out). Smem aliased into 48KB static buffer.
// ---------------------------------------------------------------------------
__global__ __launch_bounds__(256) void pass1_kernel(
    const float* __restrict__ x,
    const float* __restrict__ U, const float* __restrict__ Wgate,
    const float* __restrict__ bgate)
{
    __shared__ __align__(16) unsigned char smem_buf[49152];
    float4* sx4  = (float4*)smem_buf;               // [2048] fp32 x over 4 tokens
    float4* tb4  = (float4*)(smem_buf + 32768);     // [512]  t = f*u
    float4* fb4  = (float4*)(smem_buf + 40960);     // [512]  f
    float (*red)[4] = (float(*)[4])(smem_buf + 32768);  // aliases tb4 (used before)
    float4 (*red2)[4][32] = (float4(*)[4][32])smem_buf; // aliases sx4 (used after)

    const int tid = threadIdx.x;
    const size_t tok0 = (size_t)blockIdx.x * 4;
    const int b = (int)(tok0 >> 11);
    const int tloc0 = (int)(tok0 & (Tn - 1));
    const float* x0 = x + tok0 * Dn;

    // ---- load 4 x rows interleaved + per-token sumsq ----
    float ss0 = 0.f, ss1 = 0.f, ss2 = 0.f, ss3 = 0.f;
    #pragma unroll
    for (int i = 0; i < 8; i++) {
        int d = tid + i * 256;
        float v0 = x0[d], v1 = x0[Dn + d], v2 = x0[2 * Dn + d], v3 = x0[3 * Dn + d];
        sx4[d] = make_float4(v0, v1, v2, v3);
        ss0 += v0 * v0; ss1 += v1 * v1; ss2 += v2 * v2; ss3 += v3 * v3;
    }
    #pragma unroll
    for (int o = 16; o; o >>= 1) {
        ss0 += __shfl_xor_sync(~0u, ss0, o); ss1 += __shfl_xor_sync(~0u, ss1, o);
        ss2 += __shfl_xor_sync(~0u, ss2, o); ss3 += __shfl_xor_sync(~0u, ss3, o);
    }
    if ((tid & 31) == 0) {
        int w = tid >> 5;
        red[w][0] = ss0; red[w][1] = ss1; red[w][2] = ss2; red[w][3] = ss3;
    }
    __syncthreads();
    float t0s = 0.f, t1s = 0.f, t2s = 0.f, t3s = 0.f;
    #pragma unroll
    for (int w = 0; w < 8; w++) {
        t0s += red[w][0]; t1s += red[w][1]; t2s += red[w][2]; t3s += red[w][3];
    }
    const float4 rst = make_float4(rsqrtf(t0s * (1.0f / Dn) + 1e-6f),
                                   rsqrtf(t1s * (1.0f / Dn) + 1e-6f),
                                   rsqrtf(t2s * (1.0f / Dn) + 1e-6f),
                                   rsqrtf(t3s * (1.0f / Dn) + 1e-6f));
    __syncthreads();   // red reads done before tb4 writes

    // ---- fp32 gather-dot: u, f, t for 4 tokens ----
    #pragma unroll
    for (int pp = 0; pp < 2; pp++) {
        int p = tid + pp * 256;
        float4 a = make_float4(0.f, 0.f, 0.f, 0.f);
        #pragma unroll
        for (int k = 0; k < Kn; k++) {
            int2 e = d_pw_ssm[k * Pn + p];
            float w = __int_as_float(e.y);
            float4 xv = sx4[e.x];
            a.x += xv.x * w; a.y += xv.y * w; a.z += xv.z * w; a.w += xv.w * w;
        }
        float4 u = make_float4(a.x * rst.x, a.y * rst.y, a.z * rst.z, a.w * rst.w);
        float4 f = make_float4(sigmoidf_fast(u.x), sigmoidf_fast(u.y),
                               sigmoidf_fast(u.z), sigmoidf_fast(u.w));
        fb4[p] = f;
        tb4[p] = make_float4(f.x * u.x, f.y * u.y, f.z * u.z, f.w * u.w);
        g_f[(tok0 + 0) * Pn + p] = __float2half_rn(f.x);
        g_f[(tok0 + 1) * Pn + p] = __float2half_rn(f.y);
        g_f[(tok0 + 2) * Pn + p] = __float2half_rn(f.z);
        g_f[(tok0 + 3) * Pn + p] = __float2half_rn(f.w);
    }
    __syncthreads();

    // ---- einsum: z[r] = t . U[:,r] ; pre-gate[r] = f . Wgate[:,r] ----
    const int which  = tid >> 7;        // warp-uniform
    const int stripe = (tid >> 5) & 3;
    const int r      = tid & 31;
    const float* Wb = (which ? Wgate : U) + (size_t)(stripe * 128) * Rn + r;
    const float4* buf = (which ? fb4 : tb4) + stripe * 128;
    float4 acc = make_float4(0.f, 0.f, 0.f, 0.f);
    #pragma unroll 8
    for (int p = 0; p < 128; p++) {
        float w = Wb[p * Rn];
        float4 t = buf[p];
        acc.x += t.x * w; acc.y += t.y * w; acc.z += t.z * w; acc.w += t.w * w;
    }
    red2[which][stripe][r] = acc;   // lives in dead sx4 region
    __syncthreads();
    if (tid < 64) {
        int wh = tid >> 5, rr = tid & 31;
        float4 a0 = red2[wh][0][rr], a1 = red2[wh][1][rr];
        float4 a2 = red2[wh][2][rr], a3 = red2[wh][3][rr];
        float4 v = make_float4(a0.x + a1.x + a2.x + a3.x, a0.y + a1.y + a2.y + a3.y,
                               a0.z + a1.z + a2.z + a3.z, a0.w + a1.w + a2.w + a3.w);
        size_t o = ((size_t)(b * Rn + rr)) * Tn + tloc0;
        if (wh == 0) {
            *(float4*)(g_z + o) = v;
        } else {
            float bg = bgate[rr];
            float4 l = make_float4(sigmoidf_fast(v.x + bg), sigmoidf_fast(v.y + bg),
                                   sigmoidf_fast(v.z + bg), sigmoidf_fast(v.w + bg));
            *(float4*)(g_lam + o) = l;
        }
    }
}

// ---------------------------------------------------------------------------
// Scan: one block per (b,r), 256 threads x 8 steps, block-level affine scan.
// ---------------------------------------------------------------------------
__global__ __launch_bounds__(256) void scan_kernel(
    const float* __restrict__ state, float* __restrict__ state_out)
{
    const int br = blockIdx.x;         // b*32 + r
    const int b = br >> 5, r = br & 31;
    const size_t base = (size_t)br * Tn;
    const int tid = threadIdx.x;
    const int t0 = tid * 8;

    float4 za = *(const float4*)(g_z + base + t0);
    float4 zb = *(const float4*)(g_z + base + t0 + 4);
    float4 la = *(const float4*)(g_lam + base + t0);
    float4 lb = *(const float4*)(g_lam + base + t0 + 4);

    float a = la.x, bb = za.x;
    bb = la.y * bb + za.y;  a = la.y * a;
    bb = la.z * bb + za.z;  a = la.z * a;
    bb = la.w * bb + za.w;  a = la.w * a;
    bb = lb.x * bb + zb.x;  a = lb.x * a;
    bb = lb.y * bb + zb.y;  a = lb.y * a;
    bb = lb.z * bb + zb.z;  a = lb.z * a;
    bb = lb.w * bb + zb.w;  a = lb.w * a;

    const int lane = tid & 31, wid = tid >> 5;
    float A = a, Bv = bb;
    #pragma unroll
    for (int off = 1; off < 32; off <<= 1) {
        float Ap = __shfl_up_sync(~0u, A, off);
        float Bp = __shfl_up_sync(~0u, Bv, off);
        if (lane >= off) { Bv = A * Bp + Bv; A = A * Ap; }
    }
    __shared__ float wa[8], wb[8];
    if (lane == 31) { wa[wid] = A; wb[wid] = Bv; }
    __syncthreads();

    float pa = 1.f, pb = 0.f;
    #pragma unroll
    for (int w = 0; w < 8; w++) {
        if (w < wid) { pb = wa[w] * pb + wb[w]; pa = wa[w] * pa; }
    }
    float Aex = __shfl_up_sync(~0u, A, 1);
    float Bex = __shfl_up_sync(~0u, Bv, 1);
    if (lane == 0) { Aex = 1.f; Bex = 0.f; }

    const float s0 = state[b * Rn + r];
    float s = Aex * (pa * s0 + pb) + Bex;

    float4 o0, o1;
    s = la.x * s + za.x; o0.x = s;
    s = la.y * s + za.y; o0.y = s;
    s = la.z * s + za.z; o0.z = s;
    s = la.w * s + za.w; o0.w = s;
    s = lb.x * s + zb.x; o1.x = s;
    s = lb.y * s + zb.y; o1.y = s;
    s = lb.z * s + zb.z; o1.z = s;
    s = lb.w * s + zb.w; o1.w = s;
    *(float4*)(g_S + base + t0) = o0;
    *(float4*)(g_S + base + t0 + 4) = o1;

    if (tid == 255 && state_out != nullptr)
        state_out[b * Rn + r] = s;
}

// ---------------------------------------------------------------------------
// Pass 3: 4 tokens/block. c_ssm from stored f; MLP gather from bf16 mirror
// (safe: feeds x_out only, residual-dominated).
// Dynamic smem: sx4 fp32 (32KB) | sxh bf16 (16KB) | cb4 (8KB) = 56KB
// ---------------------------------------------------------------------------
__global__ __launch_bounds__(256) void pass3_kernel(
    const float* __restrict__ x, const float* __restrict__ V,
    float* __restrict__ out)
{
    extern __shared__ __align__(16) unsigned char dsm[];
    float4* sx4 = (float4*)dsm;                       // [2048] fp32 x_after
    uint2*  sxh = (uint2*)(dsm + 32768);              // [2048] bf16 mirror
    float4* cb4 = (float4*)(dsm + 49152);             // [512]
    __shared__ float sS[4][32];
    __shared__ float red[8][4];
    __shared__ float s_rstd[4];

    const int tid = threadIdx.x;
    const size_t tok0 = (size_t)blockIdx.x * 4;
    const int b = (int)(tok0 >> 11);
    const int tloc0 = (int)(tok0 & (Tn - 1));
    const float* x0 = x + tok0 * Dn;

    if (tid < 128) {
        int rr = tid >> 2, tt = tid & 3;
        sS[tt][rr] = g_S[((size_t)(b * Rn + rr)) * Tn + tloc0 + tt];
    }
    __syncthreads();

    // ---- c_ssm[p] = f_ssm * (S . V[:,p]) * so ----
    #pragma unroll
    for (int pp = 0; pp < 2; pp++) {
        int p = tid + pp * 256;
        float4 tl = make_float4(0.f, 0.f, 0.f, 0.f);
        #pragma unroll
        for (int rr = 0; rr < Rn; rr++) {
            float w = V[rr * Pn + p];
            tl.x += sS[0][rr] * w; tl.y += sS[1][rr] * w;
            tl.z += sS[2][rr] * w; tl.w += sS[3][rr] * w;
        }
        float so = d_so_ssm[p];
        float f0 = __half2float(g_f[(tok0 + 0) * Pn + p]);
        float f1 = __half2float(g_f[(tok0 + 1) * Pn + p]);
        float f2 = __half2float(g_f[(tok0 + 2) * Pn + p]);
        float f3 = __half2float(g_f[(tok0 + 3) * Pn + p]);
        cb4[p] = make_float4(f0 * tl.x * so, f1 * tl.y * so,
                             f2 * tl.z * so, f3 * tl.w * so);
    }
    __syncthreads();

    // ---- x_after = x + broadcast(c_ssm); fp32 + bf16 mirror; sumsq ----
    float ss0 = 0.f, ss1 = 0.f, ss2 = 0.f, ss3 = 0.f;
    #pragma unroll
    for (int i = 0; i < 8; i++) {
        int d = tid + i * 256;
        float4 c = cb4[d >> 2];
        float v0 = x0[d]          + c.x;
        float v1 = x0[Dn + d]     + c.y;
        float v2 = x0[2 * Dn + d] + c.z;
        float v3 = x0[3 * Dn + d] + c.w;
        sx4[d] = make_float4(v0, v1, v2, v3);
        sxh[d] = pack_bf16x4(v0, v1, v2, v3);
        ss0 += v0 * v0; ss1 += v1 * v1; ss2 += v2 * v2; ss3 += v3 * v3;
    }
    #pragma unroll
    for (int o = 16; o; o >>= 1) {
        ss0 += __shfl_xor_sync(~0u, ss0, o); ss1 += __shfl_xor_sync(~0u, ss1, o);
        ss2 += __shfl_xor_sync(~0u, ss2, o); ss3 += __shfl_xor_sync(~0u, ss3, o);
    }
    if ((tid & 31) == 0) {
        int w = tid >> 5;
        red[w][0] = ss0; red[w][1] = ss1; red[w][2] = ss2; red[w][3] = ss3;
    }
    __syncthreads();
    if (tid < 4) {
        float t = 0.f;
        #pragma unroll
        for (int w = 0; w < 8; w++) t += red[w][tid];
        s_rstd[tid] = rsqrtf(t * (1.0f / Dn) + 1e-6f);
    }
    __syncthreads();
    const float4 rst = make_float4(s_rstd[0], s_rstd[1], s_rstd[2], s_rstd[3]);

    // ---- MLP gather from bf16 mirror ----
    #pragma unroll
    for (int pp = 0; pp < 2; pp++) {
        int p = tid + pp * 256;
        float a0 = 0.f, a1 = 0.f, a2 = 0.f, a3 = 0.f;
        #pragma unroll
        for (int k = 0; k < Kn; k++) {
            int2 e = d_pw_mlp[k * Pn + p];
            float w = __int_as_float(e.y);
            uint2 xv = sxh[e.x];
            a0 += __int_as_float(xv.x << 16)         * w;
            a1 += __int_as_float(xv.x & 0xffff0000u) * w;
            a2 += __int_as_float(xv.y << 16)         * w;
            a3 += __int_as_float(xv.y & 0xffff0000u) * w;
        }
        float4 u = make_float4(a0 * rst.x, a1 * rst.y, a2 * rst.z, a3 * rst.w);
        float4 f = make_float4(sigmoidf_fast(u.x), sigmoidf_fast(u.y),
                               sigmoidf_fast(u.z), sigmoidf_fast(u.w));
        float so = d_so_mlp[p];
        cb4[p] = make_float4(f.x * u.x * so, f.y * u.y * so,
                             f.z * u.z * so, f.w * u.w * so);
    }
    __syncthreads();

    // ---- x_out = x_after + broadcast(c_mlp), coalesced per-token stores ----
    #pragma unroll
    for (int i = 0; i < 8; i++) {
        int d = tid + i * 256;
        float4 v = sx4[d];
        float4 c = cb4[d >> 2];
        out[(tok0 + 0) * Dn + d] = v.x + c.x;
        out[(tok0 + 1) * Dn + d] = v.y + c.y;
        out[(tok0 + 2) * Dn + d] = v.z + c.z;
        out[(tok0 + 3) * Dn + d] = v.w + c.w;
    }
}

// ---------------------------------------------------------------------------
extern "C" void kernel_launch(void* const* d_in, const int* in_sizes, int n_in,
                              void* d_out, int out_size)
{
    const float* x        = (const float*)d_in[0];
    const float* state    = (const float*)d_in[1];
    const float* g1       = (const float*)d_in[2];
    const float* g2       = (const float*)d_in[3];
    const int*   idx_ssm  = (const int*)  d_in[4];
    const float* wg_ssm   = (const float*)d_in[5];
    const int*   idx_mlp  = (const int*)  d_in[6];
    const float* wg_mlp   = (const float*)d_in[7];
    const float* Wp_ssm   = (const float*)d_in[8];
    const float* Wout_ssm = (const float*)d_in[9];
    const float* Wp_mlp   = (const float*)d_in[10];
    const float* Wout_mlp = (const float*)d_in[11];
    const float* U        = (const float*)d_in[12];
    const float* V        = (const float*)d_in[13];
    const float* Wgate    = (const float*)d_in[14];
    const float* bgate    = (const float*)d_in[15];
    float* out = (float*)d_out;

    float* state_out = (out_size >= Bn * Tn * Dn + Bn * Rn)
                     ? (out + (size_t)Bn * Tn * Dn) : nullptr;

    static bool attr_set = false;
    if (!attr_set) {
        cudaFuncSetAttribute(pass3_kernel,
                             cudaFuncAttributeMaxDynamicSharedMemorySize, 57344);
        attr_set = true;
    }

    precompute_kernel<<<1, 512>>>(wg_ssm, wg_mlp, Wp_ssm, Wout_ssm,
                                  Wp_mlp, Wout_mlp, idx_ssm, idx_mlp, g1, g2);
    pass1_kernel<<<Bn * Tn / 4, 256>>>(x, U, Wgate, bgate);
    scan_kernel<<<Bn * Rn, 256>>>(state, state_out);
    pass3_kernel<<<Bn * Tn / 4, 256, 57344>>>(x, V, out);
}

// round 8
// speedup vs baseline: 6.6118x; 1.0663x over previous
#include <cuda_runtime.h>
#include <cuda_fp16.h>
#include <cuda_bf16.h>
#include <cstdint>

#define Bn 4
#define Tn 2048
#define Dn 2048
#define Pn 512
#define Kn 16
#define Rn 32
#define NEXC 409   // int(0.8 * 512)

// ---- static scratch (no allocations allowed) ----
__device__ int2   d_pw_ssm[Kn * Pn];   // transposed packed (idx, weight-bits)
__device__ int2   d_pw_mlp[Kn * Pn];
__device__ float  d_so_ssm[Pn];
__device__ float  d_so_mlp[Pn];
__device__ float  g_z  [Bn * Rn * Tn];   // [b][r][t]
__device__ float  g_lam[Bn * Rn * Tn];
__device__ float  g_S  [Bn * Rn * Tn];
__device__ __half g_f  [(size_t)Bn * Tn * Pn];  // [token][p]

__device__ __forceinline__ float sigmoidf_fast(float u) {
    return 1.0f / (1.0f + __expf(-u));
}

__device__ __forceinline__ unsigned pack_bf16x2(float a, float b) {
    __nv_bfloat162 p = __floats2bfloat162_rn(a, b);
    return *reinterpret_cast<unsigned*>(&p);
}
__device__ __forceinline__ float bf_lo(unsigned v) { return __int_as_float(v << 16); }
__device__ __forceinline__ float bf_hi(unsigned v) { return __int_as_float(v & 0xffff0000u); }

// ---------------------------------------------------------------------------
// Precompute: quant scalars + transposed packed gather tables.
// ---------------------------------------------------------------------------
__global__ void precompute_kernel(
    const float* __restrict__ wg_ssm, const float* __restrict__ wg_mlp,
    const float* __restrict__ Wp_ssm, const float* __restrict__ Wout_ssm,
    const float* __restrict__ Wp_mlp, const float* __restrict__ Wout_mlp,
    const int*   __restrict__ idx_ssm, const int* __restrict__ idx_mlp,
    const float* __restrict__ g1, const float* __restrict__ g2)
{
    int p = threadIdx.x;
    if (p >= Pn) return;
    float sign = (p < NEXC) ? 1.0f : -1.0f;

    float s = 0.f;
    #pragma unroll
    for (int k = 0; k < Kn; k++) s += fabsf(Wp_ssm[p * Kn + k]);
    float sp_ssm = sign * s * (1.0f / Kn);

    s = 0.f;
    #pragma unroll
    for (int a = 0; a < 4; a++) s += fabsf(Wout_ssm[p * 4 + a]);
    d_so_ssm[p] = sign * s * 0.25f;

    s = 0.f;
    #pragma unroll
    for (int k = 0; k < Kn; k++) s += fabsf(Wp_mlp[p * Kn + k]);
    float sp_mlp = sign * s * (1.0f / Kn);

    s = 0.f;
    #pragma unroll
    for (int a = 0; a < 4; a++) s += fabsf(Wout_mlp[p * 4 + a]);
    d_so_mlp[p] = sign * s * 0.25f;

    #pragma unroll
    for (int k = 0; k < Kn; k++) {
        int ds = idx_ssm[p * Kn + k];
        float ws = sp_ssm * wg_ssm[p * Kn + k] * g1[ds];
        d_pw_ssm[k * Pn + p] = make_int2(ds, __float_as_int(ws));
        int dm = idx_mlp[p * Kn + k];
        float wm = sp_mlp * wg_mlp[p * Kn + k] * g2[dm];
        d_pw_mlp[k * Pn + p] = make_int2(dm, __float_as_int(wm));
    }
}

// ---------------------------------------------------------------------------
// Pass 1: 8 tokens/block, 512 threads. FP32 gathers (state path precision).
// Dyn smem 96KB: sxa/sxb fp32 x (64KB) | tba/tbb/fba/fbb (32KB).
// red2 aliases the (dead-by-then) sx region.
// ---------------------------------------------------------------------------
__global__ void __launch_bounds__(512, 2) pass1_kernel(
    const float* __restrict__ x,
    const float* __restrict__ U, const float* __restrict__ Wgate,
    const float* __restrict__ bgate)
{
    extern __shared__ __align__(16) unsigned char dsm[];
    float4* sxa = (float4*)dsm;                   // [2048] tokens 0-3
    float4* sxb = (float4*)(dsm + 32768);         // [2048] tokens 4-7
    float4* tba = (float4*)(dsm + 65536);         // [512]
    float4* tbb = (float4*)(dsm + 73728);
    float4* fba = (float4*)(dsm + 81920);
    float4* fbb = (float4*)(dsm + 90112);
    float4 (*r2a)[8][32] = (float4(*)[8][32])dsm;            // alias sxa (dead)
    float4 (*r2b)[8][32] = (float4(*)[8][32])(dsm + 8192);
    __shared__ float red[16][8];
    __shared__ float s_rstd[8];

    const int tid = threadIdx.x;
    const size_t tok0 = (size_t)blockIdx.x * 8;
    const int b = (int)(tok0 >> 11);
    const int tloc0 = (int)(tok0 & (Tn - 1));
    const float* x0 = x + tok0 * Dn;

    // ---- load 8 x rows interleaved + per-token sumsq ----
    float ss[8] = {0.f, 0.f, 0.f, 0.f, 0.f, 0.f, 0.f, 0.f};
    #pragma unroll
    for (int i = 0; i < 4; i++) {
        int d = tid + i * 512;
        float v[8];
        #pragma unroll
        for (int j = 0; j < 8; j++) { v[j] = x0[(size_t)j * Dn + d]; ss[j] += v[j] * v[j]; }
        sxa[d] = make_float4(v[0], v[1], v[2], v[3]);
        sxb[d] = make_float4(v[4], v[5], v[6], v[7]);
    }
    #pragma unroll
    for (int o = 16; o; o >>= 1) {
        #pragma unroll
        for (int j = 0; j < 8; j++) ss[j] += __shfl_xor_sync(~0u, ss[j], o);
    }
    if ((tid & 31) == 0) {
        int w = tid >> 5;
        #pragma unroll
        for (int j = 0; j < 8; j++) red[w][j] = ss[j];
    }
    __syncthreads();
    if (tid < 8) {
        float t = 0.f;
        #pragma unroll
        for (int w = 0; w < 16; w++) t += red[w][tid];
        s_rstd[tid] = rsqrtf(t * (1.0f / Dn) + 1e-6f);
    }
    __syncthreads();
    float rs[8];
    #pragma unroll
    for (int j = 0; j < 8; j++) rs[j] = s_rstd[j];

    // ---- fp32 gather-dot: u, f, t for 8 tokens; one p per thread ----
    {
        const int p = tid;
        float a[8] = {0.f, 0.f, 0.f, 0.f, 0.f, 0.f, 0.f, 0.f};
        #pragma unroll
        for (int k = 0; k < Kn; k++) {
            int2 e = d_pw_ssm[k * Pn + p];
            float w = __int_as_float(e.y);
            float4 xa = sxa[e.x];
            float4 xb = sxb[e.x];
            a[0] += xa.x * w; a[1] += xa.y * w; a[2] += xa.z * w; a[3] += xa.w * w;
            a[4] += xb.x * w; a[5] += xb.y * w; a[6] += xb.z * w; a[7] += xb.w * w;
        }
        float u[8], f[8];
        #pragma unroll
        for (int j = 0; j < 8; j++) {
            u[j] = a[j] * rs[j];
            f[j] = sigmoidf_fast(u[j]);
        }
        fba[p] = make_float4(f[0], f[1], f[2], f[3]);
        fbb[p] = make_float4(f[4], f[5], f[6], f[7]);
        tba[p] = make_float4(f[0] * u[0], f[1] * u[1], f[2] * u[2], f[3] * u[3]);
        tbb[p] = make_float4(f[4] * u[4], f[5] * u[5], f[6] * u[6], f[7] * u[7]);
        #pragma unroll
        for (int j = 0; j < 8; j++)
            g_f[(tok0 + j) * Pn + p] = __float2half_rn(f[j]);
    }
    __syncthreads();

    // ---- einsum: z[r] = t . U[:,r] ; pre-gate[r] = f . Wgate[:,r] ----
    const int which  = tid >> 8;        // 0 -> z, 1 -> gate (warp-uniform)
    const int stripe = (tid >> 5) & 7;  // 8 stripes of 64 p
    const int r      = tid & 31;
    const float* Wb = (which ? Wgate : U) + (size_t)(stripe * 64) * Rn + r;
    const float4* bua = (which ? fba : tba) + stripe * 64;
    const float4* bub = (which ? fbb : tbb) + stripe * 64;
    float4 aa = make_float4(0.f, 0.f, 0.f, 0.f);
    float4 ab = make_float4(0.f, 0.f, 0.f, 0.f);
    #pragma unroll 8
    for (int p = 0; p < 64; p++) {
        float w = Wb[p * Rn];
        float4 ta = bua[p], tb = bub[p];
        aa.x += ta.x * w; aa.y += ta.y * w; aa.z += ta.z * w; aa.w += ta.w * w;
        ab.x += tb.x * w; ab.y += tb.y * w; ab.z += tb.z * w; ab.w += tb.w * w;
    }
    r2a[which][stripe][r] = aa;
    r2b[which][stripe][r] = ab;
    __syncthreads();
    if (tid < 64) {
        int wh = tid >> 5, rr = tid & 31;
        float4 va = make_float4(0.f, 0.f, 0.f, 0.f);
        float4 vb = make_float4(0.f, 0.f, 0.f, 0.f);
        #pragma unroll
        for (int s = 0; s < 8; s++) {
            float4 ca = r2a[wh][s][rr], cb = r2b[wh][s][rr];
            va.x += ca.x; va.y += ca.y; va.z += ca.z; va.w += ca.w;
            vb.x += cb.x; vb.y += cb.y; vb.z += cb.z; vb.w += cb.w;
        }
        size_t o = ((size_t)(b * Rn + rr)) * Tn + tloc0;
        if (wh == 0) {
            *(float4*)(g_z + o) = va;
            *(float4*)(g_z + o + 4) = vb;
        } else {
            float bg = bgate[rr];
            float4 la = make_float4(sigmoidf_fast(va.x + bg), sigmoidf_fast(va.y + bg),
                                    sigmoidf_fast(va.z + bg), sigmoidf_fast(va.w + bg));
            float4 lb = make_float4(sigmoidf_fast(vb.x + bg), sigmoidf_fast(vb.y + bg),
                                    sigmoidf_fast(vb.z + bg), sigmoidf_fast(vb.w + bg));
            *(float4*)(g_lam + o) = la;
            *(float4*)(g_lam + o + 4) = lb;
        }
    }
}

// ---------------------------------------------------------------------------
// Scan: one block per (b,r), 256 threads x 8 steps, block-level affine scan.
// ---------------------------------------------------------------------------
__global__ __launch_bounds__(256) void scan_kernel(
    const float* __restrict__ state, float* __restrict__ state_out)
{
    const int br = blockIdx.x;         // b*32 + r
    const int b = br >> 5, r = br & 31;
    const size_t base = (size_t)br * Tn;
    const int tid = threadIdx.x;
    const int t0 = tid * 8;

    float4 za = *(const float4*)(g_z + base + t0);
    float4 zb = *(const float4*)(g_z + base + t0 + 4);
    float4 la = *(const float4*)(g_lam + base + t0);
    float4 lb = *(const float4*)(g_lam + base + t0 + 4);

    float a = la.x, bb = za.x;
    bb = la.y * bb + za.y;  a = la.y * a;
    bb = la.z * bb + za.z;  a = la.z * a;
    bb = la.w * bb + za.w;  a = la.w * a;
    bb = lb.x * bb + zb.x;  a = lb.x * a;
    bb = lb.y * bb + zb.y;  a = lb.y * a;
    bb = lb.z * bb + zb.z;  a = lb.z * a;
    bb = lb.w * bb + zb.w;  a = lb.w * a;

    const int lane = tid & 31, wid = tid >> 5;
    float A = a, Bv = bb;
    #pragma unroll
    for (int off = 1; off < 32; off <<= 1) {
        float Ap = __shfl_up_sync(~0u, A, off);
        float Bp = __shfl_up_sync(~0u, Bv, off);
        if (lane >= off) { Bv = A * Bp + Bv; A = A * Ap; }
    }
    __shared__ float wa[8], wb[8];
    if (lane == 31) { wa[wid] = A; wb[wid] = Bv; }
    __syncthreads();

    float pa = 1.f, pb = 0.f;
    #pragma unroll
    for (int w = 0; w < 8; w++) {
        if (w < wid) { pb = wa[w] * pb + wb[w]; pa = wa[w] * pa; }
    }
    float Aex = __shfl_up_sync(~0u, A, 1);
    float Bex = __shfl_up_sync(~0u, Bv, 1);
    if (lane == 0) { Aex = 1.f; Bex = 0.f; }

    const float s0 = state[b * Rn + r];
    float s = Aex * (pa * s0 + pb) + Bex;

    float4 o0, o1;
    s = la.x * s + za.x; o0.x = s;
    s = la.y * s + za.y; o0.y = s;
    s = la.z * s + za.z; o0.z = s;
    s = la.w * s + za.w; o0.w = s;
    s = lb.x * s + zb.x; o1.x = s;
    s = lb.y * s + zb.y; o1.y = s;
    s = lb.z * s + zb.z; o1.z = s;
    s = lb.w * s + zb.w; o1.w = s;
    *(float4*)(g_S + base + t0) = o0;
    *(float4*)(g_S + base + t0 + 4) = o1;

    if (tid == 255 && state_out != nullptr)
        state_out[b * Rn + r] = s;
}

// ---------------------------------------------------------------------------
// Pass 3: 8 tokens/block, 512 threads. No fp32 x_after buffer: store phase
// recomputes x0 + c_ssm + c_mlp (identical FADD ordering as before).
// Dyn smem 64KB: sxh bf16 (32KB) | csa/csb (16KB) | cma/cmb (16KB).
// ---------------------------------------------------------------------------
__global__ void __launch_bounds__(512, 2) pass3_kernel(
    const float* __restrict__ x, const float* __restrict__ V,
    float* __restrict__ out)
{
    extern __shared__ __align__(16) unsigned char dsm[];
    uint4*  sxh = (uint4*)dsm;                    // [2048] bf16x8 mirror
    float4* csa = (float4*)(dsm + 32768);         // [512] c_ssm tokens 0-3
    float4* csb = (float4*)(dsm + 40960);         // [512] c_ssm tokens 4-7
    float4* cma = (float4*)(dsm + 49152);         // [512] c_mlp tokens 0-3
    float4* cmb = (float4*)(dsm + 57344);         // [512] c_mlp tokens 4-7
    __shared__ float sS[8][32];
    __shared__ float red[16][8];
    __shared__ float s_rstd[8];

    const int tid = threadIdx.x;
    const size_t tok0 = (size_t)blockIdx.x * 8;
    const int b = (int)(tok0 >> 11);
    const int tloc0 = (int)(tok0 & (Tn - 1));
    const float* x0 = x + tok0 * Dn;

    if (tid < 256) {
        int rr = tid >> 3, tt = tid & 7;
        sS[tt][rr] = g_S[((size_t)(b * Rn + rr)) * Tn + tloc0 + tt];
    }
    __syncthreads();

    // ---- c_ssm[p] = f_ssm * (S . V[:,p]) * so ----
    {
        const int p = tid;
        float tl[8] = {0.f, 0.f, 0.f, 0.f, 0.f, 0.f, 0.f, 0.f};
        #pragma unroll
        for (int rr = 0; rr < Rn; rr++) {
            float w = V[rr * Pn + p];
            #pragma unroll
            for (int j = 0; j < 8; j++) tl[j] += sS[j][rr] * w;
        }
        float so = d_so_ssm[p];
        float c[8];
        #pragma unroll
        for (int j = 0; j < 8; j++)
            c[j] = __half2float(g_f[(tok0 + j) * Pn + p]) * tl[j] * so;
        csa[p] = make_float4(c[0], c[1], c[2], c[3]);
        csb[p] = make_float4(c[4], c[5], c[6], c[7]);
    }
    __syncthreads();

    // ---- x_after = x + broadcast(c_ssm): bf16 mirror + sumsq ----
    float ss[8] = {0.f, 0.f, 0.f, 0.f, 0.f, 0.f, 0.f, 0.f};
    #pragma unroll
    for (int i = 0; i < 4; i++) {
        int d = tid + i * 512;
        int p = d >> 2;
        float4 ca = csa[p], cb = csb[p];
        float v[8];
        v[0] = x0[d]                   + ca.x;
        v[1] = x0[(size_t)1 * Dn + d]  + ca.y;
        v[2] = x0[(size_t)2 * Dn + d]  + ca.z;
        v[3] = x0[(size_t)3 * Dn + d]  + ca.w;
        v[4] = x0[(size_t)4 * Dn + d]  + cb.x;
        v[5] = x0[(size_t)5 * Dn + d]  + cb.y;
        v[6] = x0[(size_t)6 * Dn + d]  + cb.z;
        v[7] = x0[(size_t)7 * Dn + d]  + cb.w;
        #pragma unroll
        for (int j = 0; j < 8; j++) ss[j] += v[j] * v[j];
        sxh[d] = make_uint4(pack_bf16x2(v[0], v[1]), pack_bf16x2(v[2], v[3]),
                            pack_bf16x2(v[4], v[5]), pack_bf16x2(v[6], v[7]));
    }
    #pragma unroll
    for (int o = 16; o; o >>= 1) {
        #pragma unroll
        for (int j = 0; j < 8; j++) ss[j] += __shfl_xor_sync(~0u, ss[j], o);
    }
    if ((tid & 31) == 0) {
        int w = tid >> 5;
        #pragma unroll
        for (int j = 0; j < 8; j++) red[w][j] = ss[j];
    }
    __syncthreads();
    if (tid < 8) {
        float t = 0.f;
        #pragma unroll
        for (int w = 0; w < 16; w++) t += red[w][tid];
        s_rstd[tid] = rsqrtf(t * (1.0f / Dn) + 1e-6f);
    }
    __syncthreads();
    float rs[8];
    #pragma unroll
    for (int j = 0; j < 8; j++) rs[j] = s_rstd[j];

    // ---- MLP gather from bf16 mirror (feeds x_out only; bf16 safe) ----
    {
        const int p = tid;
        float a[8] = {0.f, 0.f, 0.f, 0.f, 0.f, 0.f, 0.f, 0.f};
        #pragma unroll
        for (int k = 0; k < Kn; k++) {
            int2 e = d_pw_mlp[k * Pn + p];
            float w = __int_as_float(e.y);
            uint4 xv = sxh[e.x];
            a[0] += bf_lo(xv.x) * w; a[1] += bf_hi(xv.x) * w;
            a[2] += bf_lo(xv.y) * w; a[3] += bf_hi(xv.y) * w;
            a[4] += bf_lo(xv.z) * w; a[5] += bf_hi(xv.z) * w;
            a[6] += bf_lo(xv.w) * w; a[7] += bf_hi(xv.w) * w;
        }
        float so = d_so_mlp[p];
        float c[8];
        #pragma unroll
        for (int j = 0; j < 8; j++) {
            float u = a[j] * rs[j];
            float f = sigmoidf_fast(u);
            c[j] = f * u * so;
        }
        cma[p] = make_float4(c[0], c[1], c[2], c[3]);
        cmb[p] = make_float4(c[4], c[5], c[6], c[7]);
    }
    __syncthreads();

    // ---- x_out = (x + c_ssm) + c_mlp, coalesced per-token stores ----
    #pragma unroll
    for (int i = 0; i < 4; i++) {
        int d = tid + i * 512;
        int p = d >> 2;
        float4 ca = csa[p], cb = csb[p];
        float4 ma = cma[p], mb = cmb[p];
        out[(tok0 + 0) * Dn + d] = (x0[d]                  + ca.x) + ma.x;
        out[(tok0 + 1) * Dn + d] = (x0[(size_t)1 * Dn + d] + ca.y) + ma.y;
        out[(tok0 + 2) * Dn + d] = (x0[(size_t)2 * Dn + d] + ca.z) + ma.z;
        out[(tok0 + 3) * Dn + d] = (x0[(size_t)3 * Dn + d] + ca.w) + ma.w;
        out[(tok0 + 4) * Dn + d] = (x0[(size_t)4 * Dn + d] + cb.x) + mb.x;
        out[(tok0 + 5) * Dn + d] = (x0[(size_t)5 * Dn + d] + cb.y) + mb.y;
        out[(tok0 + 6) * Dn + d] = (x0[(size_t)6 * Dn + d] + cb.z) + mb.z;
        out[(tok0 + 7) * Dn + d] = (x0[(size_t)7 * Dn + d] + cb.w) + mb.w;
    }
}

// ---------------------------------------------------------------------------
extern "C" void kernel_launch(void* const* d_in, const int* in_sizes, int n_in,
                              void* d_out, int out_size)
{
    const float* x        = (const float*)d_in[0];
    const float* state    = (const float*)d_in[1];
    const float* g1       = (const float*)d_in[2];
    const float* g2       = (const float*)d_in[3];
    const int*   idx_ssm  = (const int*)  d_in[4];
    const float* wg_ssm   = (const float*)d_in[5];
    const int*   idx_mlp  = (const int*)  d_in[6];
    const float* wg_mlp   = (const float*)d_in[7];
    const float* Wp_ssm   = (const float*)d_in[8];
    const float* Wout_ssm = (const float*)d_in[9];
    const float* Wp_mlp   = (const float*)d_in[10];
    const float* Wout_mlp = (const float*)d_in[11];
    const float* U        = (const float*)d_in[12];
    const float* V        = (const float*)d_in[13];
    const float* Wgate    = (const float*)d_in[14];
    const float* bgate    = (const float*)d_in[15];
    float* out = (float*)d_out;

    float* state_out = (out_size >= Bn * Tn * Dn + Bn * Rn)
                     ? (out + (size_t)Bn * Tn * Dn) : nullptr;

    static bool attr_set = false;
    if (!attr_set) {
        cudaFuncSetAttribute(pass1_kernel,
                             cudaFuncAttributeMaxDynamicSharedMemorySize, 98304);
        cudaFuncSetAttribute(pass3_kernel,
                             cudaFuncAttributeMaxDynamicSharedMemorySize, 65536);
        attr_set = true;
    }

    precompute_kernel<<<1, 512>>>(wg_ssm, wg_mlp, Wp_ssm, Wout_ssm,
                                  Wp_mlp, Wout_mlp, idx_ssm, idx_mlp, g1, g2);
    pass1_kernel<<<Bn * Tn / 8, 512, 98304>>>(x, U, Wgate, bgate);
    scan_kernel<<<Bn * Rn, 256>>>(state, state_out);
    pass3_kernel<<<Bn * Tn / 8, 512, 65536>>>(x, V, out);
}

// round 9
// speedup vs baseline: 6.6231x; 1.0017x over previous
#include <cuda_runtime.h>
#include <cuda_fp16.h>
#include <cuda_bf16.h>
#include <cstdint>

#define Bn 4
#define Tn 2048
#define Dn 2048
#define Pn 512
#define Kn 16
#define Rn 32
#define NEXC 409   // int(0.8 * 512)

// ---- static scratch (no allocations allowed) ----
__device__ int2   d_pw_ssm[Kn * Pn];   // transposed packed (idx, weight-bits)
__device__ int2   d_pw_mlp[Kn * Pn];
__device__ float  d_so_ssm[Pn];
__device__ float  d_so_mlp[Pn];
__device__ float  g_z  [Bn * Rn * Tn];   // [b][r][t]
__device__ float  g_lam[Bn * Rn * Tn];
__device__ float  g_S  [Bn * Rn * Tn];
__device__ __half g_f  [(size_t)Bn * Tn * Pn];  // [token][p]

__device__ __forceinline__ float sigmoidf_fast(float u) {
    return 1.0f / (1.0f + __expf(-u));
}

__device__ __forceinline__ unsigned pack_bf16x2(float a, float b) {
    __nv_bfloat162 p = __floats2bfloat162_rn(a, b);
    return *reinterpret_cast<unsigned*>(&p);
}
__device__ __forceinline__ float bf_lo(unsigned v) { return __int_as_float(v << 16); }
__device__ __forceinline__ float bf_hi(unsigned v) { return __int_as_float(v & 0xffff0000u); }

// ---------------------------------------------------------------------------
// Precompute: quant scalars + transposed packed gather tables.
// ---------------------------------------------------------------------------
__global__ void precompute_kernel(
    const float* __restrict__ wg_ssm, const float* __restrict__ wg_mlp,
    const float* __restrict__ Wp_ssm, const float* __restrict__ Wout_ssm,
    const float* __restrict__ Wp_mlp, const float* __restrict__ Wout_mlp,
    const int*   __restrict__ idx_ssm, const int* __restrict__ idx_mlp,
    const float* __restrict__ g1, const float* __restrict__ g2)
{
    int p = threadIdx.x;
    if (p >= Pn) return;
    float sign = (p < NEXC) ? 1.0f : -1.0f;

    float s = 0.f;
    #pragma unroll
    for (int k = 0; k < Kn; k++) s += fabsf(Wp_ssm[p * Kn + k]);
    float sp_ssm = sign * s * (1.0f / Kn);

    s = 0.f;
    #pragma unroll
    for (int a = 0; a < 4; a++) s += fabsf(Wout_ssm[p * 4 + a]);
    d_so_ssm[p] = sign * s * 0.25f;

    s = 0.f;
    #pragma unroll
    for (int k = 0; k < Kn; k++) s += fabsf(Wp_mlp[p * Kn + k]);
    float sp_mlp = sign * s * (1.0f / Kn);

    s = 0.f;
    #pragma unroll
    for (int a = 0; a < 4; a++) s += fabsf(Wout_mlp[p * 4 + a]);
    d_so_mlp[p] = sign * s * 0.25f;

    #pragma unroll
    for (int k = 0; k < Kn; k++) {
        int ds = idx_ssm[p * Kn + k];
        float ws = sp_ssm * wg_ssm[p * Kn + k] * g1[ds];
        d_pw_ssm[k * Pn + p] = make_int2(ds, __float_as_int(ws));
        int dm = idx_mlp[p * Kn + k];
        float wm = sp_mlp * wg_mlp[p * Kn + k] * g2[dm];
        d_pw_mlp[k * Pn + p] = make_int2(dm, __float_as_int(wm));
    }
}

// ---------------------------------------------------------------------------
// Pass 1: 8 tokens/block, 512 threads. FP32 gathers (state path precision).
// Dyn smem 96KB: sxa/sxb fp32 x (64KB) | tba/tbb/fba/fbb (32KB).
// red2 aliases the (dead-by-then) sx region.
// ---------------------------------------------------------------------------
__global__ void __launch_bounds__(512, 2) pass1_kernel(
    const float* __restrict__ x,
    const float* __restrict__ U, const float* __restrict__ Wgate,
    const float* __restrict__ bgate)
{
    extern __shared__ __align__(16) unsigned char dsm[];
    float4* sxa = (float4*)dsm;                   // [2048] tokens 0-3
    float4* sxb = (float4*)(dsm + 32768);         // [2048] tokens 4-7
    float4* tba = (float4*)(dsm + 65536);         // [512]
    float4* tbb = (float4*)(dsm + 73728);
    float4* fba = (float4*)(dsm + 81920);
    float4* fbb = (float4*)(dsm + 90112);
    float4 (*r2a)[8][32] = (float4(*)[8][32])dsm;            // alias sxa (dead)
    float4 (*r2b)[8][32] = (float4(*)[8][32])(dsm + 8192);
    __shared__ float red[16][8];
    __shared__ float s_rstd[8];

    const int tid = threadIdx.x;
    const size_t tok0 = (size_t)blockIdx.x * 8;
    const int b = (int)(tok0 >> 11);
    const int tloc0 = (int)(tok0 & (Tn - 1));
    const float* x0 = x + tok0 * Dn;

    // ---- load 8 x rows interleaved + per-token sumsq ----
    float ss[8] = {0.f, 0.f, 0.f, 0.f, 0.f, 0.f, 0.f, 0.f};
    #pragma unroll
    for (int i = 0; i < 4; i++) {
        int d = tid + i * 512;
        float v[8];
        #pragma unroll
        for (int j = 0; j < 8; j++) { v[j] = x0[(size_t)j * Dn + d]; ss[j] += v[j] * v[j]; }
        sxa[d] = make_float4(v[0], v[1], v[2], v[3]);
        sxb[d] = make_float4(v[4], v[5], v[6], v[7]);
    }
    #pragma unroll
    for (int o = 16; o; o >>= 1) {
        #pragma unroll
        for (int j = 0; j < 8; j++) ss[j] += __shfl_xor_sync(~0u, ss[j], o);
    }
    if ((tid & 31) == 0) {
        int w = tid >> 5;
        #pragma unroll
        for (int j = 0; j < 8; j++) red[w][j] = ss[j];
    }
    __syncthreads();
    if (tid < 8) {
        float t = 0.f;
        #pragma unroll
        for (int w = 0; w < 16; w++) t += red[w][tid];
        s_rstd[tid] = rsqrtf(t * (1.0f / Dn) + 1e-6f);
    }
    __syncthreads();
    float rs[8];
    #pragma unroll
    for (int j = 0; j < 8; j++) rs[j] = s_rstd[j];

    // ---- fp32 gather-dot: u, f, t for 8 tokens; one p per thread ----
    {
        const int p = tid;
        float a[8] = {0.f, 0.f, 0.f, 0.f, 0.f, 0.f, 0.f, 0.f};
        #pragma unroll
        for (int k = 0; k < Kn; k++) {
            int2 e = d_pw_ssm[k * Pn + p];
            float w = __int_as_float(e.y);
            float4 xa = sxa[e.x];
            float4 xb = sxb[e.x];
            a[0] += xa.x * w; a[1] += xa.y * w; a[2] += xa.z * w; a[3] += xa.w * w;
            a[4] += xb.x * w; a[5] += xb.y * w; a[6] += xb.z * w; a[7] += xb.w * w;
        }
        float u[8], f[8];
        #pragma unroll
        for (int j = 0; j < 8; j++) {
            u[j] = a[j] * rs[j];
            f[j] = sigmoidf_fast(u[j]);
        }
        fba[p] = make_float4(f[0], f[1], f[2], f[3]);
        fbb[p] = make_float4(f[4], f[5], f[6], f[7]);
        tba[p] = make_float4(f[0] * u[0], f[1] * u[1], f[2] * u[2], f[3] * u[3]);
        tbb[p] = make_float4(f[4] * u[4], f[5] * u[5], f[6] * u[6], f[7] * u[7]);
        #pragma unroll
        for (int j = 0; j < 8; j++)
            g_f[(tok0 + j) * Pn + p] = __float2half_rn(f[j]);
    }
    __syncthreads();

    // ---- einsum: z[r] = t . U[:,r] ; pre-gate[r] = f . Wgate[:,r] ----
    const int which  = tid >> 8;        // 0 -> z, 1 -> gate (warp-uniform)
    const int stripe = (tid >> 5) & 7;  // 8 stripes of 64 p
    const int r      = tid & 31;
    const float* Wb = (which ? Wgate : U) + (size_t)(stripe * 64) * Rn + r;
    const float4* bua = (which ? fba : tba) + stripe * 64;
    const float4* bub = (which ? fbb : tbb) + stripe * 64;
    float4 aa = make_float4(0.f, 0.f, 0.f, 0.f);
    float4 ab = make_float4(0.f, 0.f, 0.f, 0.f);
    #pragma unroll 8
    for (int p = 0; p < 64; p++) {
        float w = Wb[p * Rn];
        float4 ta = bua[p], tb = bub[p];
        aa.x += ta.x * w; aa.y += ta.y * w; aa.z += ta.z * w; aa.w += ta.w * w;
        ab.x += tb.x * w; ab.y += tb.y * w; ab.z += tb.z * w; ab.w += tb.w * w;
    }
    r2a[which][stripe][r] = aa;
    r2b[which][stripe][r] = ab;
    __syncthreads();
    if (tid < 64) {
        int wh = tid >> 5, rr = tid & 31;
        float4 va = make_float4(0.f, 0.f, 0.f, 0.f);
        float4 vb = make_float4(0.f, 0.f, 0.f, 0.f);
        #pragma unroll
        for (int s = 0; s < 8; s++) {
            float4 ca = r2a[wh][s][rr], cb = r2b[wh][s][rr];
            va.x += ca.x; va.y += ca.y; va.z += ca.z; va.w += ca.w;
            vb.x += cb.x; vb.y += cb.y; vb.z += cb.z; vb.w += cb.w;
        }
        size_t o = ((size_t)(b * Rn + rr)) * Tn + tloc0;
        if (wh == 0) {
            *(float4*)(g_z + o) = va;
            *(float4*)(g_z + o + 4) = vb;
        } else {
            float bg = bgate[rr];
            float4 la = make_float4(sigmoidf_fast(va.x + bg), sigmoidf_fast(va.y + bg),
                                    sigmoidf_fast(va.z + bg), sigmoidf_fast(va.w + bg));
            float4 lb = make_float4(sigmoidf_fast(vb.x + bg), sigmoidf_fast(vb.y + bg),
                                    sigmoidf_fast(vb.z + bg), sigmoidf_fast(vb.w + bg));
            *(float4*)(g_lam + o) = la;
            *(float4*)(g_lam + o + 4) = lb;
        }
    }
}

// ---------------------------------------------------------------------------
// Scan: one block per (b,r), 256 threads x 8 steps, block-level affine scan.
// ---------------------------------------------------------------------------
__global__ __launch_bounds__(256) void scan_kernel(
    const float* __restrict__ state, float* __restrict__ state_out)
{
    const int br = blockIdx.x;         // b*32 + r
    const int b = br >> 5, r = br & 31;
    const size_t base = (size_t)br * Tn;
    const int tid = threadIdx.x;
    const int t0 = tid * 8;

    float4 za = *(const float4*)(g_z + base + t0);
    float4 zb = *(const float4*)(g_z + base + t0 + 4);
    float4 la = *(const float4*)(g_lam + base + t0);
    float4 lb = *(const float4*)(g_lam + base + t0 + 4);

    float a = la.x, bb = za.x;
    bb = la.y * bb + za.y;  a = la.y * a;
    bb = la.z * bb + za.z;  a = la.z * a;
    bb = la.w * bb + za.w;  a = la.w * a;
    bb = lb.x * bb + zb.x;  a = lb.x * a;
    bb = lb.y * bb + zb.y;  a = lb.y * a;
    bb = lb.z * bb + zb.z;  a = lb.z * a;
    bb = lb.w * bb + zb.w;  a = lb.w * a;

    const int lane = tid & 31, wid = tid >> 5;
    float A = a, Bv = bb;
    #pragma unroll
    for (int off = 1; off < 32; off <<= 1) {
        float Ap = __shfl_up_sync(~0u, A, off);
        float Bp = __shfl_up_sync(~0u, Bv, off);
        if (lane >= off) { Bv = A * Bp + Bv; A = A * Ap; }
    }
    __shared__ float wa[8], wb[8];
    if (lane == 31) { wa[wid] = A; wb[wid] = Bv; }
    __syncthreads();

    float pa = 1.f, pb = 0.f;
    #pragma unroll
    for (int w = 0; w < 8; w++) {
        if (w < wid) { pb = wa[w] * pb + wb[w]; pa = wa[w] * pa; }
    }
    float Aex = __shfl_up_sync(~0u, A, 1);
    float Bex = __shfl_up_sync(~0u, Bv, 1);
    if (lane == 0) { Aex = 1.f; Bex = 0.f; }

    const float s0 = state[b * Rn + r];
    float s = Aex * (pa * s0 + pb) + Bex;

    float4 o0, o1;
    s = la.x * s + za.x; o0.x = s;
    s = la.y * s + za.y; o0.y = s;
    s = la.z * s + za.z; o0.z = s;
    s = la.w * s + za.w; o0.w = s;
    s = lb.x * s + zb.x; o1.x = s;
    s = lb.y * s + zb.y; o1.y = s;
    s = lb.z * s + zb.z; o1.z = s;
    s = lb.w * s + zb.w; o1.w = s;
    *(float4*)(g_S + base + t0) = o0;
    *(float4*)(g_S + base + t0 + 4) = o1;

    if (tid == 255 && state_out != nullptr)
        state_out[b * Rn + r] = s;
}

// ---------------------------------------------------------------------------
// Pass 3: 8 tokens/block, 512 threads. No fp32 x_after buffer: store phase
// recomputes x0 + c_ssm + c_mlp (identical FADD ordering as before).
// Dyn smem 64KB: sxh bf16 (32KB) | csa/csb (16KB) | cma/cmb (16KB).
// ---------------------------------------------------------------------------
__global__ void __launch_bounds__(512, 2) pass3_kernel(
    const float* __restrict__ x, const float* __restrict__ V,
    float* __restrict__ out)
{
    extern __shared__ __align__(16) unsigned char dsm[];
    uint4*  sxh = (uint4*)dsm;                    // [2048] bf16x8 mirror
    float4* csa = (float4*)(dsm + 32768);         // [512] c_ssm tokens 0-3
    float4* csb = (float4*)(dsm + 40960);         // [512] c_ssm tokens 4-7
    float4* cma = (float4*)(dsm + 49152);         // [512] c_mlp tokens 0-3
    float4* cmb = (float4*)(dsm + 57344);         // [512] c_mlp tokens 4-7
    __shared__ float sS[8][32];
    __shared__ float red[16][8];
    __shared__ float s_rstd[8];

    const int tid = threadIdx.x;
    const size_t tok0 = (size_t)blockIdx.x * 8;
    const int b = (int)(tok0 >> 11);
    const int tloc0 = (int)(tok0 & (Tn - 1));
    const float* x0 = x + tok0 * Dn;

    if (tid < 256) {
        int rr = tid >> 3, tt = tid & 7;
        sS[tt][rr] = g_S[((size_t)(b * Rn + rr)) * Tn + tloc0 + tt];
    }
    __syncthreads();

    // ---- c_ssm[p] = f_ssm * (S . V[:,p]) * so ----
    {
        const int p = tid;
        float tl[8] = {0.f, 0.f, 0.f, 0.f, 0.f, 0.f, 0.f, 0.f};
        #pragma unroll
        for (int rr = 0; rr < Rn; rr++) {
            float w = V[rr * Pn + p];
            #pragma unroll
            for (int j = 0; j < 8; j++) tl[j] += sS[j][rr] * w;
        }
        float so = d_so_ssm[p];
        float c[8];
        #pragma unroll
        for (int j = 0; j < 8; j++)
            c[j] = __half2float(g_f[(tok0 + j) * Pn + p]) * tl[j] * so;
        csa[p] = make_float4(c[0], c[1], c[2], c[3]);
        csb[p] = make_float4(c[4], c[5], c[6], c[7]);
    }
    __syncthreads();

    // ---- x_after = x + broadcast(c_ssm): bf16 mirror + sumsq ----
    float ss[8] = {0.f, 0.f, 0.f, 0.f, 0.f, 0.f, 0.f, 0.f};
    #pragma unroll
    for (int i = 0; i < 4; i++) {
        int d = tid + i * 512;
        int p = d >> 2;
        float4 ca = csa[p], cb = csb[p];
        float v[8];
        v[0] = x0[d]                   + ca.x;
        v[1] = x0[(size_t)1 * Dn + d]  + ca.y;
        v[2] = x0[(size_t)2 * Dn + d]  + ca.z;
        v[3] = x0[(size_t)3 * Dn + d]  + ca.w;
        v[4] = x0[(size_t)4 * Dn + d]  + cb.x;
        v[5] = x0[(size_t)5 * Dn + d]  + cb.y;
        v[6] = x0[(size_t)6 * Dn + d]  + cb.z;
        v[7] = x0[(size_t)7 * Dn + d]  + cb.w;
        #pragma unroll
        for (int j = 0; j < 8; j++) ss[j] += v[j] * v[j];
        sxh[d] = make_uint4(pack_bf16x2(v[0], v[1]), pack_bf16x2(v[2], v[3]),
                            pack_bf16x2(v[4], v[5]), pack_bf16x2(v[6], v[7]));
    }
    #pragma unroll
    for (int o = 16; o; o >>= 1) {
        #pragma unroll
        for (int j = 0; j < 8; j++) ss[j] += __shfl_xor_sync(~0u, ss[j], o);
    }
    if ((tid & 31) == 0) {
        int w = tid >> 5;
        #pragma unroll
        for (int j = 0; j < 8; j++) red[w][j] = ss[j];
    }
    __syncthreads();
    if (tid < 8) {
        float t = 0.f;
        #pragma unroll
        for (int w = 0; w < 16; w++) t += red[w][tid];
        s_rstd[tid] = rsqrtf(t * (1.0f / Dn) + 1e-6f);
    }
    __syncthreads();
    float rs[8];
    #pragma unroll
    for (int j = 0; j < 8; j++) rs[j] = s_rstd[j];

    // ---- MLP gather from bf16 mirror (feeds x_out only; bf16 safe) ----
    {
        const int p = tid;
        float a[8] = {0.f, 0.f, 0.f, 0.f, 0.f, 0.f, 0.f, 0.f};
        #pragma unroll
        for (int k = 0; k < Kn; k++) {
            int2 e = d_pw_mlp[k * Pn + p];
            float w = __int_as_float(e.y);
            uint4 xv = sxh[e.x];
            a[0] += bf_lo(xv.x) * w; a[1] += bf_hi(xv.x) * w;
            a[2] += bf_lo(xv.y) * w; a[3] += bf_hi(xv.y) * w;
            a[4] += bf_lo(xv.z) * w; a[5] += bf_hi(xv.z) * w;
            a[6] += bf_lo(xv.w) * w; a[7] += bf_hi(xv.w) * w;
        }
        float so = d_so_mlp[p];
        float c[8];
        #pragma unroll
        for (int j = 0; j < 8; j++) {
            float u = a[j] * rs[j];
            float f = sigmoidf_fast(u);
            c[j] = f * u * so;
        }
        cma[p] = make_float4(c[0], c[1], c[2], c[3]);
        cmb[p] = make_float4(c[4], c[5], c[6], c[7]);
    }
    __syncthreads();

    // ---- x_out = (x + c_ssm) + c_mlp, coalesced per-token stores ----
    #pragma unroll
    for (int i = 0; i < 4; i++) {
        int d = tid + i * 512;
        int p = d >> 2;
        float4 ca = csa[p], cb = csb[p];
        float4 ma = cma[p], mb = cmb[p];
        out[(tok0 + 0) * Dn + d] = (x0[d]                  + ca.x) + ma.x;
        out[(tok0 + 1) * Dn + d] = (x0[(size_t)1 * Dn + d] + ca.y) + ma.y;
        out[(tok0 + 2) * Dn + d] = (x0[(size_t)2 * Dn + d] + ca.z) + ma.z;
        out[(tok0 + 3) * Dn + d] = (x0[(size_t)3 * Dn + d] + ca.w) + ma.w;
        out[(tok0 + 4) * Dn + d] = (x0[(size_t)4 * Dn + d] + cb.x) + mb.x;
        out[(tok0 + 5) * Dn + d] = (x0[(size_t)5 * Dn + d] + cb.y) + mb.y;
        out[(tok0 + 6) * Dn + d] = (x0[(size_t)6 * Dn + d] + cb.z) + mb.z;
        out[(tok0 + 7) * Dn + d] = (x0[(size_t)7 * Dn + d] + cb.w) + mb.w;
    }
}

// ---------------------------------------------------------------------------
extern "C" void kernel_launch(void* const* d_in, const int* in_sizes, int n_in,
                              void* d_out, int out_size)
{
    const float* x        = (const float*)d_in[0];
    const float* state    = (const float*)d_in[1];
    const float* g1       = (const float*)d_in[2];
    const float* g2       = (const float*)d_in[3];
    const int*   idx_ssm  = (const int*)  d_in[4];
    const float* wg_ssm   = (const float*)d_in[5];
    const int*   idx_mlp  = (const int*)  d_in[6];
    const float* wg_mlp   = (const float*)d_in[7];
    const float* Wp_ssm   = (const float*)d_in[8];
    const float* Wout_ssm = (const float*)d_in[9];
    const float* Wp_mlp   = (const float*)d_in[10];
    const float* Wout_mlp = (const float*)d_in[11];
    const float* U        = (const float*)d_in[12];
    const float* V        = (const float*)d_in[13];
    const float* Wgate    = (const float*)d_in[14];
    const float* bgate    = (const float*)d_in[15];
    float* out = (float*)d_out;

    float* state_out = (out_size >= Bn * Tn * Dn + Bn * Rn)
                     ? (out + (size_t)Bn * Tn * Dn) : nullptr;

    static bool attr_set = false;
    if (!attr_set) {
        cudaFuncSetAttribute(pass1_kernel,
                             cudaFuncAttributeMaxDynamicSharedMemorySize, 98304);
        cudaFuncSetAttribute(pass3_kernel,
                             cudaFuncAttributeMaxDynamicSharedMemorySize, 65536);
        attr_set = true;
    }

    precompute_kernel<<<1, 512>>>(wg_ssm, wg_mlp, Wp_ssm, Wout_ssm,
                                  Wp_mlp, Wout_mlp, idx_ssm, idx_mlp, g1, g2);
    pass1_kernel<<<Bn * Tn / 8, 512, 98304>>>(x, U, Wgate, bgate);
    scan_kernel<<<Bn * Rn, 256>>>(state, state_out);
    pass3_kernel<<<Bn * Tn / 8, 512, 65536>>>(x, V, out);
}

// round 10
// speedup vs baseline: 7.8304x; 1.1823x over previous
#include <cuda_runtime.h>
#include <cuda_fp16.h>
#include <cuda_bf16.h>
#include <cstdint>

#define Bn 4
#define Tn 2048
#define Dn 2048
#define Pn 512
#define Kn 16
#define Rn 32
#define NEXC 409   // int(0.8 * 512)

// ---- static scratch (no allocations allowed) ----
__device__ int2   d_pw_ssm[Kn * Pn];   // transposed packed (idx, weight-bits)
__device__ int2   d_pw_mlp[Kn * Pn];
__device__ float  d_so_ssm[Pn];
__device__ float  d_so_mlp[Pn];
__device__ float  g_z  [Bn * Rn * Tn];   // [b][r][t]
__device__ float  g_lam[Bn * Rn * Tn];
__device__ float  g_S  [Bn * Rn * Tn];
__device__ __half g_f  [(size_t)Bn * Tn * Pn];  // [token][p]

__device__ __forceinline__ float sigmoidf_fast(float u) {
    return 1.0f / (1.0f + __expf(-u));
}

__device__ __forceinline__ unsigned pack_h16x2(float a, float b) {
    __half2 p = __floats2half2_rn(a, b);
    return *reinterpret_cast<unsigned*>(&p);
}
__device__ __forceinline__ float2 h2f2(unsigned u) {
    __half2 h = *reinterpret_cast<__half2*>(&u);
    return __half22float2(h);
}
__device__ __forceinline__ unsigned pack_bf16x2(float a, float b) {
    __nv_bfloat162 p = __floats2bfloat162_rn(a, b);
    return *reinterpret_cast<unsigned*>(&p);
}
__device__ __forceinline__ float bf_lo(unsigned v) { return __int_as_float(v << 16); }
__device__ __forceinline__ float bf_hi(unsigned v) { return __int_as_float(v & 0xffff0000u); }

// ---------------------------------------------------------------------------
// Precompute (8 blocks x 64 thr): quant scalars + transposed gather tables.
// ---------------------------------------------------------------------------
__global__ void precompute_kernel(
    const float* __restrict__ wg_ssm, const float* __restrict__ wg_mlp,
    const float* __restrict__ Wp_ssm, const float* __restrict__ Wout_ssm,
    const float* __restrict__ Wp_mlp, const float* __restrict__ Wout_mlp,
    const int*   __restrict__ idx_ssm, const int* __restrict__ idx_mlp,
    const float* __restrict__ g1, const float* __restrict__ g2)
{
    int p = blockIdx.x * 64 + threadIdx.x;
    if (p >= Pn) return;
    float sign = (p < NEXC) ? 1.0f : -1.0f;

    float s = 0.f;
    #pragma unroll
    for (int k = 0; k < Kn; k++) s += fabsf(Wp_ssm[p * Kn + k]);
    float sp_ssm = sign * s * (1.0f / Kn);

    s = 0.f;
    #pragma unroll
    for (int a = 0; a < 4; a++) s += fabsf(Wout_ssm[p * 4 + a]);
    d_so_ssm[p] = sign * s * 0.25f;

    s = 0.f;
    #pragma unroll
    for (int k = 0; k < Kn; k++) s += fabsf(Wp_mlp[p * Kn + k]);
    float sp_mlp = sign * s * (1.0f / Kn);

    s = 0.f;
    #pragma unroll
    for (int a = 0; a < 4; a++) s += fabsf(Wout_mlp[p * 4 + a]);
    d_so_mlp[p] = sign * s * 0.25f;

    #pragma unroll
    for (int k = 0; k < Kn; k++) {
        int ds = idx_ssm[p * Kn + k];
        float ws = sp_ssm * wg_ssm[p * Kn + k] * g1[ds];
        d_pw_ssm[k * Pn + p] = make_int2(ds, __float_as_int(ws));
        int dm = idx_mlp[p * Kn + k];
        float wm = sp_mlp * wg_mlp[p * Kn + k] * g2[dm];
        d_pw_mlp[k * Pn + p] = make_int2(dm, __float_as_int(wm));
    }
}

// ---------------------------------------------------------------------------
// Pass 1: 8 tokens/block, 512 threads. FP16x8 gather mirror (11-bit mantissa:
// 8x less error than bf16's failed attempt; predicted state err ~2e-4).
// Dyn smem 64KB: sxh fp16 (32KB) | tba/tbb/fba/fbb (32KB). red2 aliases sxh.
// ---------------------------------------------------------------------------
__global__ void __launch_bounds__(512, 2) pass1_kernel(
    const float* __restrict__ x,
    const float* __restrict__ U, const float* __restrict__ Wgate,
    const float* __restrict__ bgate)
{
    extern __shared__ __align__(16) unsigned char dsm[];
    uint4*  sxh = (uint4*)dsm;                    // [2048] fp16x8 over tokens
    float4* tba = (float4*)(dsm + 32768);         // [512]
    float4* tbb = (float4*)(dsm + 40960);
    float4* fba = (float4*)(dsm + 49152);
    float4* fbb = (float4*)(dsm + 57344);
    float4 (*r2a)[8][32] = (float4(*)[8][32])dsm;          // alias sxh (dead)
    float4 (*r2b)[8][32] = (float4(*)[8][32])(dsm + 8192);
    __shared__ float red[16][8];
    __shared__ float s_rstd[8];

    const int tid = threadIdx.x;
    const size_t tok0 = (size_t)blockIdx.x * 8;
    const int b = (int)(tok0 >> 11);
    const int tloc0 = (int)(tok0 & (Tn - 1));
    const float* x0 = x + tok0 * Dn;

    // ---- vectorized load: thread owns d = 4*tid..4*tid+3 ----
    {
        float ss[8];
        uint4 mir[4];
        #pragma unroll
        for (int jj = 0; jj < 4; jj++) {
            float4 xe = ((const float4*)(x0 + (size_t)(2 * jj)     * Dn))[tid];
            float4 xo = ((const float4*)(x0 + (size_t)(2 * jj + 1) * Dn))[tid];
            ss[2 * jj]     = xe.x * xe.x + xe.y * xe.y + xe.z * xe.z + xe.w * xe.w;
            ss[2 * jj + 1] = xo.x * xo.x + xo.y * xo.y + xo.z * xo.z + xo.w * xo.w;
            unsigned* m = (unsigned*)mir;   // mir[q].comp(jj) = pack(tok2jj, tok2jj+1) at d=4t+q
            m[0 * 4 + jj] = pack_h16x2(xe.x, xo.x);
            m[1 * 4 + jj] = pack_h16x2(xe.y, xo.y);
            m[2 * 4 + jj] = pack_h16x2(xe.z, xo.z);
            m[3 * 4 + jj] = pack_h16x2(xe.w, xo.w);
        }
        #pragma unroll
        for (int q = 0; q < 4; q++) sxh[4 * tid + q] = mir[q];
        #pragma unroll
        for (int o = 16; o; o >>= 1) {
            #pragma unroll
            for (int j = 0; j < 8; j++) ss[j] += __shfl_xor_sync(~0u, ss[j], o);
        }
        if ((tid & 31) == 0) {
            int w = tid >> 5;
            #pragma unroll
            for (int j = 0; j < 8; j++) red[w][j] = ss[j];
        }
    }
    __syncthreads();
    if (tid < 8) {
        float t = 0.f;
        #pragma unroll
        for (int w = 0; w < 16; w++) t += red[w][tid];
        s_rstd[tid] = rsqrtf(t * (1.0f / Dn) + 1e-6f);
    }
    __syncthreads();
    float rs[8];
    #pragma unroll
    for (int j = 0; j < 8; j++) rs[j] = s_rstd[j];

    // ---- fp16 gather-dot: u, f, t for 8 tokens; one p per thread ----
    {
        const int p = tid;
        float a[8] = {0.f, 0.f, 0.f, 0.f, 0.f, 0.f, 0.f, 0.f};
        #pragma unroll
        for (int k = 0; k < Kn; k++) {
            int2 e = d_pw_ssm[k * Pn + p];
            float w = __int_as_float(e.y);
            uint4 xv = sxh[e.x];
            // packing: word q of uint4 at d holds token-pairs? No: layout is
            // sxh[d] = {pack(t0,t1), pack(t2,t3), pack(t4,t5), pack(t6,t7)}?
            // Actually above: mir[q] word jj = pack(tok 2jj, tok 2jj+1) at d=4t+q,
            // so sxh[d].x = (t0,t1), .y = (t2,t3), .z = (t4,t5), .w = (t6,t7).
            float2 p0 = h2f2(xv.x), p1 = h2f2(xv.y), p2 = h2f2(xv.z), p3 = h2f2(xv.w);
            a[0] += p0.x * w; a[1] += p0.y * w;
            a[2] += p1.x * w; a[3] += p1.y * w;
            a[4] += p2.x * w; a[5] += p2.y * w;
            a[6] += p3.x * w; a[7] += p3.y * w;
        }
        float u[8], f[8];
        #pragma unroll
        for (int j = 0; j < 8; j++) {
            u[j] = a[j] * rs[j];
            f[j] = sigmoidf_fast(u[j]);
        }
        fba[p] = make_float4(f[0], f[1], f[2], f[3]);
        fbb[p] = make_float4(f[4], f[5], f[6], f[7]);
        tba[p] = make_float4(f[0] * u[0], f[1] * u[1], f[2] * u[2], f[3] * u[3]);
        tbb[p] = make_float4(f[4] * u[4], f[5] * u[5], f[6] * u[6], f[7] * u[7]);
        #pragma unroll
        for (int j = 0; j < 8; j++)
            g_f[(tok0 + j) * Pn + p] = __float2half_rn(f[j]);
    }
    __syncthreads();

    // ---- einsum: z[r] = t . U[:,r] ; pre-gate[r] = f . Wgate[:,r] ----
    const int which  = tid >> 8;        // 0 -> z, 1 -> gate (warp-uniform)
    const int stripe = (tid >> 5) & 7;  // 8 stripes of 64 p
    const int r      = tid & 31;
    const float* Wb = (which ? Wgate : U) + (size_t)(stripe * 64) * Rn + r;
    const float4* bua = (which ? fba : tba) + stripe * 64;
    const float4* bub = (which ? fbb : tbb) + stripe * 64;
    float4 aa = make_float4(0.f, 0.f, 0.f, 0.f);
    float4 ab = make_float4(0.f, 0.f, 0.f, 0.f);
    #pragma unroll 8
    for (int p = 0; p < 64; p++) {
        float w = Wb[p * Rn];
        float4 ta = bua[p], tb = bub[p];
        aa.x += ta.x * w; aa.y += ta.y * w; aa.z += ta.z * w; aa.w += ta.w * w;
        ab.x += tb.x * w; ab.y += tb.y * w; ab.z += tb.z * w; ab.w += tb.w * w;
    }
    r2a[which][stripe][r] = aa;
    r2b[which][stripe][r] = ab;
    __syncthreads();
    if (tid < 64) {
        int wh = tid >> 5, rr = tid & 31;
        float4 va = make_float4(0.f, 0.f, 0.f, 0.f);
        float4 vb = make_float4(0.f, 0.f, 0.f, 0.f);
        #pragma unroll
        for (int s = 0; s < 8; s++) {
            float4 ca = r2a[wh][s][rr], cb = r2b[wh][s][rr];
            va.x += ca.x; va.y += ca.y; va.z += ca.z; va.w += ca.w;
            vb.x += cb.x; vb.y += cb.y; vb.z += cb.z; vb.w += cb.w;
        }
        size_t o = ((size_t)(b * Rn + rr)) * Tn + tloc0;
        if (wh == 0) {
            *(float4*)(g_z + o) = va;
            *(float4*)(g_z + o + 4) = vb;
        } else {
            float bg = bgate[rr];
            float4 la = make_float4(sigmoidf_fast(va.x + bg), sigmoidf_fast(va.y + bg),
                                    sigmoidf_fast(va.z + bg), sigmoidf_fast(va.w + bg));
            float4 lb = make_float4(sigmoidf_fast(vb.x + bg), sigmoidf_fast(vb.y + bg),
                                    sigmoidf_fast(vb.z + bg), sigmoidf_fast(vb.w + bg));
            *(float4*)(g_lam + o) = la;
            *(float4*)(g_lam + o + 4) = lb;
        }
    }
}

// ---------------------------------------------------------------------------
// Scan: one block per (b,r), 256 threads x 8 steps, block-level affine scan.
// ---------------------------------------------------------------------------
__global__ __launch_bounds__(256) void scan_kernel(
    const float* __restrict__ state, float* __restrict__ state_out)
{
    const int br = blockIdx.x;         // b*32 + r
    const int b = br >> 5, r = br & 31;
    const size_t base = (size_t)br * Tn;
    const int tid = threadIdx.x;
    const int t0 = tid * 8;

    float4 za = *(const float4*)(g_z + base + t0);
    float4 zb = *(const float4*)(g_z + base + t0 + 4);
    float4 la = *(const float4*)(g_lam + base + t0);
    float4 lb = *(const float4*)(g_lam + base + t0 + 4);

    float a = la.x, bb = za.x;
    bb = la.y * bb + za.y;  a = la.y * a;
    bb = la.z * bb + za.z;  a = la.z * a;
    bb = la.w * bb + za.w;  a = la.w * a;
    bb = lb.x * bb + zb.x;  a = lb.x * a;
    bb = lb.y * bb + zb.y;  a = lb.y * a;
    bb = lb.z * bb + zb.z;  a = lb.z * a;
    bb = lb.w * bb + zb.w;  a = lb.w * a;

    const int lane = tid & 31, wid = tid >> 5;
    float A = a, Bv = bb;
    #pragma unroll
    for (int off = 1; off < 32; off <<= 1) {
        float Ap = __shfl_up_sync(~0u, A, off);
        float Bp = __shfl_up_sync(~0u, Bv, off);
        if (lane >= off) { Bv = A * Bp + Bv; A = A * Ap; }
    }
    __shared__ float wa[8], wb[8];
    if (lane == 31) { wa[wid] = A; wb[wid] = Bv; }
    __syncthreads();

    float pa = 1.f, pb = 0.f;
    #pragma unroll
    for (int w = 0; w < 8; w++) {
        if (w < wid) { pb = wa[w] * pb + wb[w]; pa = wa[w] * pa; }
    }
    float Aex = __shfl_up_sync(~0u, A, 1);
    float Bex = __shfl_up_sync(~0u, Bv, 1);
    if (lane == 0) { Aex = 1.f; Bex = 0.f; }

    const float s0 = state[b * Rn + r];
    float s = Aex * (pa * s0 + pb) + Bex;

    float4 o0, o1;
    s = la.x * s + za.x; o0.x = s;
    s = la.y * s + za.y; o0.y = s;
    s = la.z * s + za.z; o0.z = s;
    s = la.w * s + za.w; o0.w = s;
    s = lb.x * s + zb.x; o1.x = s;
    s = lb.y * s + zb.y; o1.y = s;
    s = lb.z * s + zb.z; o1.z = s;
    s = lb.w * s + zb.w; o1.w = s;
    *(float4*)(g_S + base + t0) = o0;
    *(float4*)(g_S + base + t0 + 4) = o1;

    if (tid == 255 && state_out != nullptr)
        state_out[b * Rn + r] = s;
}

// ---------------------------------------------------------------------------
// Pass 3: 8 tokens/block, 512 threads. bf16 gather mirror (x_out only: safe).
// Vectorized phases: thread owns d = 4*tid..4*tid+3 -> port p = tid.
// Dyn smem 64KB: sxh bf16 (32KB) | csa/csb (16KB) | cma/cmb (16KB).
// ---------------------------------------------------------------------------
__global__ void __launch_bounds__(512, 2) pass3_kernel(
    const float* __restrict__ x, const float* __restrict__ V,
    float* __restrict__ out)
{
    extern __shared__ __align__(16) unsigned char dsm[];
    uint4*  sxh = (uint4*)dsm;                    // [2048] bf16x8 mirror
    float4* csa = (float4*)(dsm + 32768);         // [512] c_ssm tokens 0-3
    float4* csb = (float4*)(dsm + 40960);         // [512] c_ssm tokens 4-7
    float4* cma = (float4*)(dsm + 49152);         // [512] c_mlp tokens 0-3
    float4* cmb = (float4*)(dsm + 57344);         // [512] c_mlp tokens 4-7
    __shared__ float sS[8][32];
    __shared__ float red[16][8];
    __shared__ float s_rstd[8];

    const int tid = threadIdx.x;
    const size_t tok0 = (size_t)blockIdx.x * 8;
    const int b = (int)(tok0 >> 11);
    const int tloc0 = (int)(tok0 & (Tn - 1));
    const float* x0 = x + tok0 * Dn;

    if (tid < 256) {
        int rr = tid >> 3, tt = tid & 7;
        sS[tt][rr] = g_S[((size_t)(b * Rn + rr)) * Tn + tloc0 + tt];
    }
    __syncthreads();

    // ---- c_ssm[p] = f_ssm * (S . V[:,p]) * so ----
    {
        const int p = tid;
        float tl[8] = {0.f, 0.f, 0.f, 0.f, 0.f, 0.f, 0.f, 0.f};
        #pragma unroll
        for (int rr = 0; rr < Rn; rr++) {
            float w = V[rr * Pn + p];
            #pragma unroll
            for (int j = 0; j < 8; j++) tl[j] += sS[j][rr] * w;
        }
        float so = d_so_ssm[p];
        float c[8];
        #pragma unroll
        for (int j = 0; j < 8; j++)
            c[j] = __half2float(g_f[(tok0 + j) * Pn + p]) * tl[j] * so;
        csa[p] = make_float4(c[0], c[1], c[2], c[3]);
        csb[p] = make_float4(c[4], c[5], c[6], c[7]);
    }
    __syncthreads();

    // ---- x_after = x + c_ssm[tid broadcast]: bf16 mirror + sumsq ----
    {
        const float4 ca = csa[tid], cb = csb[tid];
        const float cs[8] = {ca.x, ca.y, ca.z, ca.w, cb.x, cb.y, cb.z, cb.w};
        float ss[8];
        uint4 mir[4];
        #pragma unroll
        for (int jj = 0; jj < 4; jj++) {
            float4 xe = ((const float4*)(x0 + (size_t)(2 * jj)     * Dn))[tid];
            float4 xo = ((const float4*)(x0 + (size_t)(2 * jj + 1) * Dn))[tid];
            float ce = cs[2 * jj], co = cs[2 * jj + 1];
            float ve0 = xe.x + ce, ve1 = xe.y + ce, ve2 = xe.z + ce, ve3 = xe.w + ce;
            float vo0 = xo.x + co, vo1 = xo.y + co, vo2 = xo.z + co, vo3 = xo.w + co;
            ss[2 * jj]     = ve0 * ve0 + ve1 * ve1 + ve2 * ve2 + ve3 * ve3;
            ss[2 * jj + 1] = vo0 * vo0 + vo1 * vo1 + vo2 * vo2 + vo3 * vo3;
            unsigned* m = (unsigned*)mir;
            m[0 * 4 + jj] = pack_bf16x2(ve0, vo0);
            m[1 * 4 + jj] = pack_bf16x2(ve1, vo1);
            m[2 * 4 + jj] = pack_bf16x2(ve2, vo2);
            m[3 * 4 + jj] = pack_bf16x2(ve3, vo3);
        }
        #pragma unroll
        for (int q = 0; q < 4; q++) sxh[4 * tid + q] = mir[q];
        #pragma unroll
        for (int o = 16; o; o >>= 1) {
            #pragma unroll
            for (int j = 0; j < 8; j++) ss[j] += __shfl_xor_sync(~0u, ss[j], o);
        }
        if ((tid & 31) == 0) {
            int w = tid >> 5;
            #pragma unroll
            for (int j = 0; j < 8; j++) red[w][j] = ss[j];
        }
    }
    __syncthreads();
    if (tid < 8) {
        float t = 0.f;
        #pragma unroll
        for (int w = 0; w < 16; w++) t += red[w][tid];
        s_rstd[tid] = rsqrtf(t * (1.0f / Dn) + 1e-6f);
    }
    __syncthreads();
    float rs[8];
    #pragma unroll
    for (int j = 0; j < 8; j++) rs[j] = s_rstd[j];

    // ---- MLP gather from bf16 mirror ----
    // sxh[d] words: .x=(t0,t1) .y=(t2,t3) .z=(t4,t5) .w=(t6,t7), bf16 lo=first
    {
        const int p = tid;
        float a[8] = {0.f, 0.f, 0.f, 0.f, 0.f, 0.f, 0.f, 0.f};
        #pragma unroll
        for (int k = 0; k < Kn; k++) {
            int2 e = d_pw_mlp[k * Pn + p];
            float w = __int_as_float(e.y);
            uint4 xv = sxh[e.x];
            a[0] += bf_lo(xv.x) * w; a[1] += bf_hi(xv.x) * w;
            a[2] += bf_lo(xv.y) * w; a[3] += bf_hi(xv.y) * w;
            a[4] += bf_lo(xv.z) * w; a[5] += bf_hi(xv.z) * w;
            a[6] += bf_lo(xv.w) * w; a[7] += bf_hi(xv.w) * w;
        }
        float so = d_so_mlp[p];
        float c[8];
        #pragma unroll
        for (int j = 0; j < 8; j++) {
            float u = a[j] * rs[j];
            float f = sigmoidf_fast(u);
            c[j] = f * u * so;
        }
        cma[p] = make_float4(c[0], c[1], c[2], c[3]);
        cmb[p] = make_float4(c[4], c[5], c[6], c[7]);
    }
    __syncthreads();

    // ---- x_out = (x + c_ssm) + c_mlp, vectorized float4 stores ----
    {
        const float4 ca = csa[tid], cb = csb[tid];
        const float4 ma = cma[tid], mb = cmb[tid];
        const float cs[8] = {ca.x, ca.y, ca.z, ca.w, cb.x, cb.y, cb.z, cb.w};
        const float cm[8] = {ma.x, ma.y, ma.z, ma.w, mb.x, mb.y, mb.z, mb.w};
        #pragma unroll
        for (int j = 0; j < 8; j++) {
            float4 xv = ((const float4*)(x0 + (size_t)j * Dn))[tid];
            float c1 = cs[j], c2 = cm[j];
            float4 o;
            o.x = (xv.x + c1) + c2;
            o.y = (xv.y + c1) + c2;
            o.z = (xv.z + c1) + c2;
            o.w = (xv.w + c1) + c2;
            ((float4*)(out + (tok0 + j) * Dn))[tid] = o;
        }
    }
}

// ---------------------------------------------------------------------------
extern "C" void kernel_launch(void* const* d_in, const int* in_sizes, int n_in,
                              void* d_out, int out_size)
{
    const float* x        = (const float*)d_in[0];
    const float* state    = (const float*)d_in[1];
    const float* g1       = (const float*)d_in[2];
    const float* g2       = (const float*)d_in[3];
    const int*   idx_ssm  = (const int*)  d_in[4];
    const float* wg_ssm   = (const float*)d_in[5];
    const int*   idx_mlp  = (const int*)  d_in[6];
    const float* wg_mlp   = (const float*)d_in[7];
    const float* Wp_ssm   = (const float*)d_in[8];
    const float* Wout_ssm = (const float*)d_in[9];
    const float* Wp_mlp   = (const float*)d_in[10];
    const float* Wout_mlp = (const float*)d_in[11];
    const float* U        = (const float*)d_in[12];
    const float* V        = (const float*)d_in[13];
    const float* Wgate    = (const float*)d_in[14];
    const float* bgate    = (const float*)d_in[15];
    float* out = (float*)d_out;

    float* state_out = (out_size >= Bn * Tn * Dn + Bn * Rn)
                     ? (out + (size_t)Bn * Tn * Dn) : nullptr;

    static bool attr_set = false;
    if (!attr_set) {
        cudaFuncSetAttribute(pass1_kernel,
                             cudaFuncAttributeMaxDynamicSharedMemorySize, 65536);
        cudaFuncSetAttribute(pass3_kernel,
                             cudaFuncAttributeMaxDynamicSharedMemorySize, 65536);
        attr_set = true;
    }

    precompute_kernel<<<8, 64>>>(wg_ssm, wg_mlp, Wp_ssm, Wout_ssm,
                                 Wp_mlp, Wout_mlp, idx_ssm, idx_mlp, g1, g2);
    pass1_kernel<<<Bn * Tn / 8, 512, 65536>>>(x, U, Wgate, bgate);
    scan_kernel<<<Bn * Rn, 256>>>(state, state_out);
    pass3_kernel<<<Bn * Tn / 8, 512, 65536>>>(x, V, out);
}